// round 1
// baseline (speedup 1.0000x reference)
#include <cuda_runtime.h>

#define T_SEQ   4096
#define D_EMBD  1024
#define N_HEADS 16
#define D_HEAD  64

// Scratch (device globals — no runtime allocation allowed)
__device__ float g_kqv[(size_t)T_SEQ * 3 * D_EMBD];   // 48 MB
__device__ float g_att[(size_t)T_SEQ * D_EMBD];       // 16 MB

// ---------------------------------------------------------------------------
// GEMM: C = A(MxK) @ B(KxN) + bias,  row-major, M,N multiples of 128, K of 16
// 256 threads, BM=BN=128, BK=16, 8x8 per-thread microtile.
// ---------------------------------------------------------------------------
#define GBM 128
#define GBN 128
#define GBK 16

__global__ __launch_bounds__(256, 2)
void gemm_bias_kernel(const float* __restrict__ A, const float* __restrict__ B,
                      const float* __restrict__ bias, float* __restrict__ C,
                      int M, int N, int K)
{
    __shared__ float As[GBK][GBM];   // A tile stored transposed: As[k][m]
    __shared__ float Bs[GBK][GBN];

    const int tid  = threadIdx.x;
    const int row0 = blockIdx.y * GBM;
    const int col0 = blockIdx.x * GBN;
    const int trow = (tid >> 4) * 8;   // 0..120
    const int tcol = (tid & 15) * 8;   // 0..120

    float acc[8][8];
    #pragma unroll
    for (int i = 0; i < 8; i++)
        #pragma unroll
        for (int j = 0; j < 8; j++) acc[i][j] = 0.0f;

    for (int k0 = 0; k0 < K; k0 += GBK) {
        // Load A tile (128x16) -> As transposed. 512 float4 total, 2 per thread.
        #pragma unroll
        for (int l = 0; l < 2; l++) {
            int idx = tid + l * 256;            // 0..511
            int ar  = idx >> 2;                  // 0..127
            int ac  = (idx & 3) * 4;             // 0,4,8,12
            float4 v = *(const float4*)(A + (size_t)(row0 + ar) * K + k0 + ac);
            As[ac + 0][ar] = v.x;
            As[ac + 1][ar] = v.y;
            As[ac + 2][ar] = v.z;
            As[ac + 3][ar] = v.w;
        }
        // Load B tile (16x128). 512 float4 total, 2 per thread.
        #pragma unroll
        for (int l = 0; l < 2; l++) {
            int idx = tid + l * 256;
            int br  = idx >> 5;                  // 0..15
            int bc  = (idx & 31) * 4;            // 0..124
            *(float4*)&Bs[br][bc] =
                *(const float4*)(B + (size_t)(k0 + br) * N + col0 + bc);
        }
        __syncthreads();

        #pragma unroll
        for (int kk = 0; kk < GBK; kk++) {
            float4 a0 = *(const float4*)&As[kk][trow];
            float4 a1 = *(const float4*)&As[kk][trow + 4];
            float4 b0 = *(const float4*)&Bs[kk][tcol];
            float4 b1 = *(const float4*)&Bs[kk][tcol + 4];
            float a[8] = {a0.x, a0.y, a0.z, a0.w, a1.x, a1.y, a1.z, a1.w};
            float b[8] = {b0.x, b0.y, b0.z, b0.w, b1.x, b1.y, b1.z, b1.w};
            #pragma unroll
            for (int i = 0; i < 8; i++)
                #pragma unroll
                for (int j = 0; j < 8; j++)
                    acc[i][j] += a[i] * b[j];
        }
        __syncthreads();
    }

    // Epilogue: add bias, store float4
    float bv[8];
    #pragma unroll
    for (int j = 0; j < 8; j++) bv[j] = bias[col0 + tcol + j];

    #pragma unroll
    for (int i = 0; i < 8; i++) {
        float4 v0, v1;
        v0.x = acc[i][0] + bv[0]; v0.y = acc[i][1] + bv[1];
        v0.z = acc[i][2] + bv[2]; v0.w = acc[i][3] + bv[3];
        v1.x = acc[i][4] + bv[4]; v1.y = acc[i][5] + bv[5];
        v1.z = acc[i][6] + bv[6]; v1.w = acc[i][7] + bv[7];
        float* cp = C + (size_t)(row0 + trow + i) * N + col0 + tcol;
        *(float4*)(cp)     = v0;
        *(float4*)(cp + 4) = v1;
    }
}

// ---------------------------------------------------------------------------
// Causal (no-softmax) attention: out = tril(Q K^T) V, per head.
// One CTA per (128-row tile, head). O kept in registers; S staged in smem.
// ---------------------------------------------------------------------------
#define QS_STRIDE 65     // padded (kills 8-row-spaced bank conflicts)
#define KT_STRIDE 128    // d-major K; rows 16B-aligned for LDS.128
#define SS_STRIDE 129    // padded
#define ATTN_SMEM ((128 * QS_STRIDE + 64 * KT_STRIDE + 128 * 64 + 128 * SS_STRIDE) * 4)

__global__ __launch_bounds__(256, 1)
void attn_kernel(const float* __restrict__ kqv, float* __restrict__ att)
{
    extern __shared__ float sm[];
    float* Qs = sm;                          // [128][QS_STRIDE]  q rows (natural)
    float* Kt = Qs + 128 * QS_STRIDE;        // [64][KT_STRIDE]   k d-major (transposed)
    float* Vs = Kt + 64 * KT_STRIDE;         // [128][64]         v natural
    float* Ss = Vs + 128 * 64;               // [128][SS_STRIDE]  scores tile

    const int i   = 31 - blockIdx.x;         // heavy tiles first
    const int h   = blockIdx.y;
    const int tid = threadIdx.x;
    const int row0 = i * 128;

    const int ldg = 3 * D_EMBD;
    const float* qg = kqv + D_EMBD     + h * D_HEAD;   // split order: k, q, v
    const float* kg = kqv              + h * D_HEAD;
    const float* vg = kqv + 2 * D_EMBD + h * D_HEAD;

    // Load Q tile (128 x 64)
    #pragma unroll
    for (int l = 0; l < 8; l++) {
        int idx = tid + l * 256;            // 0..2047
        int r   = idx >> 4;                  // 0..127
        int c   = (idx & 15) * 4;            // 0..60
        float4 v = *(const float4*)(qg + (size_t)(row0 + r) * ldg + c);
        Qs[r * QS_STRIDE + c + 0] = v.x;
        Qs[r * QS_STRIDE + c + 1] = v.y;
        Qs[r * QS_STRIDE + c + 2] = v.z;
        Qs[r * QS_STRIDE + c + 3] = v.w;
    }

    const int trow  = (tid >> 4) * 8;       // rows for both phases
    const int tcol  = (tid & 15) * 8;       // phase-1 cols
    const int tcol2 = (tid & 15) * 4;       // phase-2 cols

    float o[8][4];
    #pragma unroll
    for (int ii = 0; ii < 8; ii++)
        #pragma unroll
        for (int jj = 0; jj < 4; jj++) o[ii][jj] = 0.0f;

    for (int j = 0; j <= i; j++) {
        __syncthreads();   // prior phase-1/2 reads done before overwriting tiles

        // Load K block transposed (d-major) + V block natural
        #pragma unroll
        for (int l = 0; l < 8; l++) {
            int idx = tid + l * 256;
            int r   = idx >> 4;
            int c   = (idx & 15) * 4;
            const float* kp = kg + (size_t)(j * 128 + r) * ldg + c;
            float4 kv = *(const float4*)kp;
            Kt[(c + 0) * KT_STRIDE + r] = kv.x;
            Kt[(c + 1) * KT_STRIDE + r] = kv.y;
            Kt[(c + 2) * KT_STRIDE + r] = kv.z;
            Kt[(c + 3) * KT_STRIDE + r] = kv.w;
            const float* vp = vg + (size_t)(j * 128 + r) * ldg + c;
            *(float4*)&Vs[r * 64 + c] = *(const float4*)vp;
        }
        __syncthreads();

        // Phase 1: S = Q @ K^T   (128x128, kdim = 64), masked on diagonal block
        {
            float s[8][8];
            #pragma unroll
            for (int ii = 0; ii < 8; ii++)
                #pragma unroll
                for (int jj = 0; jj < 8; jj++) s[ii][jj] = 0.0f;

            #pragma unroll 4
            for (int k = 0; k < 64; k++) {
                float a[8];
                #pragma unroll
                for (int ii = 0; ii < 8; ii++)
                    a[ii] = Qs[(trow + ii) * QS_STRIDE + k];
                float4 b0 = *(const float4*)&Kt[k * KT_STRIDE + tcol];
                float4 b1 = *(const float4*)&Kt[k * KT_STRIDE + tcol + 4];
                float b[8] = {b0.x, b0.y, b0.z, b0.w, b1.x, b1.y, b1.z, b1.w};
                #pragma unroll
                for (int ii = 0; ii < 8; ii++)
                    #pragma unroll
                    for (int jj = 0; jj < 8; jj++)
                        s[ii][jj] += a[ii] * b[jj];
            }

            const bool diag = (j == i);
            #pragma unroll
            for (int ii = 0; ii < 8; ii++) {
                #pragma unroll
                for (int jj = 0; jj < 8; jj++) {
                    float v = s[ii][jj];
                    if (diag && (tcol + jj > trow + ii)) v = 0.0f;
                    Ss[(trow + ii) * SS_STRIDE + tcol + jj] = v;
                }
            }
        }
        __syncthreads();

        // Phase 2: O += S(128x128) @ V(128x64)
        #pragma unroll 2
        for (int k = 0; k < 128; k++) {
            float a[8];
            #pragma unroll
            for (int ii = 0; ii < 8; ii++)
                a[ii] = Ss[(trow + ii) * SS_STRIDE + k];
            float4 bv = *(const float4*)&Vs[k * 64 + tcol2];
            #pragma unroll
            for (int ii = 0; ii < 8; ii++) {
                o[ii][0] += a[ii] * bv.x;
                o[ii][1] += a[ii] * bv.y;
                o[ii][2] += a[ii] * bv.z;
                o[ii][3] += a[ii] * bv.w;
            }
        }
    }

    // Write O to att in (t, h*d) layout
    #pragma unroll
    for (int ii = 0; ii < 8; ii++) {
        float4 v = make_float4(o[ii][0], o[ii][1], o[ii][2], o[ii][3]);
        *(float4*)(att + (size_t)(row0 + trow + ii) * D_EMBD + h * D_HEAD + tcol2) = v;
    }
}

// ---------------------------------------------------------------------------
extern "C" void kernel_launch(void* const* d_in, const int* in_sizes, int n_in,
                              void* d_out, int out_size)
{
    const float* x  = (const float*)d_in[0];
    const float* W1 = (const float*)d_in[1];
    const float* b1 = (const float*)d_in[2];
    const float* W2 = (const float*)d_in[3];
    const float* b2 = (const float*)d_in[4];
    float* out = (float*)d_out;

    float *kqv, *att;
    cudaGetSymbolAddress((void**)&kqv, g_kqv);
    cudaGetSymbolAddress((void**)&att, g_att);

    // kqv = x @ W1 + b1
    gemm_bias_kernel<<<dim3(3 * D_EMBD / 128, T_SEQ / 128), 256>>>(
        x, W1, b1, kqv, T_SEQ, 3 * D_EMBD, D_EMBD);

    // att = causal-masked (Q K^T) V  per head
    cudaFuncSetAttribute(attn_kernel,
                         cudaFuncAttributeMaxDynamicSharedMemorySize, ATTN_SMEM);
    attn_kernel<<<dim3(T_SEQ / 128, N_HEADS), 256, ATTN_SMEM>>>(kqv, att);

    // out = att @ W2 + b2
    gemm_bias_kernel<<<dim3(D_EMBD / 128, T_SEQ / 128), 256>>>(
        att, W2, b2, out, T_SEQ, D_EMBD, D_EMBD);
}

// round 3
// speedup vs baseline: 2.4288x; 2.4288x over previous
#include <cuda_runtime.h>
#include <cuda_bf16.h>
#include <cstdint>

#define T_SEQ   4096
#define D_EMBD  1024
#define N_HEADS 16
#define D_HEAD  64

// Scratch (device globals — no runtime allocation allowed)
__device__ float g_kqv[(size_t)T_SEQ * 3 * D_EMBD];   // 48 MB
__device__ float g_att[(size_t)T_SEQ * D_EMBD];       // 16 MB

// ---------------------------------------------------------------------------
// Warp-level MMA helpers (sm_80+ path; compiles under compute_103)
// ---------------------------------------------------------------------------
__device__ __forceinline__ uint32_t smem_u32(const void* p) {
    uint32_t a;
    asm("{ .reg .u64 t; cvta.to.shared.u64 t, %1; cvt.u32.u64 %0, t; }"
        : "=r"(a) : "l"(p));
    return a;
}

__device__ __forceinline__ void ldsm4(uint32_t& r0, uint32_t& r1, uint32_t& r2,
                                      uint32_t& r3, uint32_t addr) {
    asm volatile("ldmatrix.sync.aligned.m8n8.x4.shared.b16 {%0,%1,%2,%3}, [%4];"
                 : "=r"(r0), "=r"(r1), "=r"(r2), "=r"(r3) : "r"(addr));
}
__device__ __forceinline__ void ldsm4t(uint32_t& r0, uint32_t& r1, uint32_t& r2,
                                       uint32_t& r3, uint32_t addr) {
    asm volatile("ldmatrix.sync.aligned.m8n8.x4.trans.shared.b16 {%0,%1,%2,%3}, [%4];"
                 : "=r"(r0), "=r"(r1), "=r"(r2), "=r"(r3) : "r"(addr));
}
__device__ __forceinline__ void mma_bf16(float* c, const uint32_t* a,
                                         uint32_t b0, uint32_t b1) {
    asm volatile(
        "mma.sync.aligned.m16n8k16.row.col.f32.bf16.bf16.f32 "
        "{%0,%1,%2,%3}, {%4,%5,%6,%7}, {%8,%9}, {%0,%1,%2,%3};"
        : "+f"(c[0]), "+f"(c[1]), "+f"(c[2]), "+f"(c[3])
        : "r"(a[0]), "r"(a[1]), "r"(a[2]), "r"(a[3]), "r"(b0), "r"(b1));
}

// hi/lo bf16 split, packing two adjacent values into a bf16x2 word each
__device__ __forceinline__ void split2(float v0, float v1, uint32_t& hi, uint32_t& lo) {
    __nv_bfloat16 h0 = __float2bfloat16(v0), h1 = __float2bfloat16(v1);
    float r0 = v0 - __bfloat162float(h0);
    float r1 = v1 - __bfloat162float(h1);
    __nv_bfloat16 l0 = __float2bfloat16(r0), l1 = __float2bfloat16(r1);
    hi = (uint32_t)__bfloat16_as_ushort(h0) | ((uint32_t)__bfloat16_as_ushort(h1) << 16);
    lo = (uint32_t)__bfloat16_as_ushort(l0) | ((uint32_t)__bfloat16_as_ushort(l1) << 16);
}

// ---------------------------------------------------------------------------
// GEMM (bf16x3): C[M,N] = A[M,K] @ B[K,N] + bias. BM=BN=128, BK=32.
// 8 warps: warp grid 2(m) x 4(n), warp tile 64x32.
// smem pitches: A rows 32 bf16 + 8 pad = 80B; B rows 128 bf16 + 8 pad = 272B.
// ---------------------------------------------------------------------------
#define G_AHI 0
#define G_ALO 10240
#define G_BHI 20480
#define G_BLO 29184
#define G_SMEM 37888

__global__ __launch_bounds__(256, 1)
void gemm_tc(const float* __restrict__ A, const float* __restrict__ B,
             const float* __restrict__ bias, float* __restrict__ C,
             int M, int N, int K)
{
    extern __shared__ char sm[];
    const uint32_t smb = smem_u32(sm);
    const int tid = threadIdx.x;
    const int w = tid >> 5, lane = tid & 31;
    const int wm = w >> 2, wn = w & 3;
    const int row0 = blockIdx.y * 128, col0 = blockIdx.x * 128;

    float acc[4][4][4];
    #pragma unroll
    for (int a = 0; a < 4; a++)
        #pragma unroll
        for (int b = 0; b < 4; b++)
            #pragma unroll
            for (int cc = 0; cc < 4; cc++) acc[a][b][cc] = 0.0f;

    const int a_r = tid >> 3, a_c = (tid & 7) * 4;   // A chunk 128x32
    const int b_r = tid >> 5, b_c = (tid & 31) * 4;  // B chunk 32x128

    float4 ra[4], rb[4];
    #pragma unroll
    for (int l = 0; l < 4; l++) {
        ra[l] = *(const float4*)(A + (size_t)(row0 + a_r + l * 32) * K + a_c);
        rb[l] = *(const float4*)(B + (size_t)(b_r + l * 8) * N + col0 + b_c);
    }

    const int nchunk = K >> 5;
    for (int kc = 0; kc < nchunk; kc++) {
        // convert + STS current chunk
        #pragma unroll
        for (int l = 0; l < 4; l++) {
            uint32_t h0, l0, h1, l1;
            split2(ra[l].x, ra[l].y, h0, l0);
            split2(ra[l].z, ra[l].w, h1, l1);
            uint32_t off = (uint32_t)((a_r + l * 32) * 80 + a_c * 2);
            *(uint2*)(sm + G_AHI + off) = make_uint2(h0, h1);
            *(uint2*)(sm + G_ALO + off) = make_uint2(l0, l1);
            split2(rb[l].x, rb[l].y, h0, l0);
            split2(rb[l].z, rb[l].w, h1, l1);
            off = (uint32_t)((b_r + l * 8) * 272 + b_c * 2);
            *(uint2*)(sm + G_BHI + off) = make_uint2(h0, h1);
            *(uint2*)(sm + G_BLO + off) = make_uint2(l0, l1);
        }
        __syncthreads();

        // prefetch next chunk (hidden under MMA)
        if (kc + 1 < nchunk) {
            int k0 = (kc + 1) * 32;
            #pragma unroll
            for (int l = 0; l < 4; l++) {
                ra[l] = *(const float4*)(A + (size_t)(row0 + a_r + l * 32) * K + k0 + a_c);
                rb[l] = *(const float4*)(B + (size_t)(k0 + b_r + l * 8) * N + col0 + b_c);
            }
        }

        #pragma unroll
        for (int ks = 0; ks < 2; ks++) {
            uint32_t ah[4][4], al[4][4], bh[2][4], bl[2][4];
            uint32_t a_off = (uint32_t)((wm * 64 + (lane & 15)) * 80 +
                                        (ks * 16 + (lane >> 4) * 8) * 2);
            #pragma unroll
            for (int tm = 0; tm < 4; tm++) {
                uint32_t ad = smb + G_AHI + a_off + tm * 16 * 80;
                ldsm4(ah[tm][0], ah[tm][1], ah[tm][2], ah[tm][3], ad);
                ldsm4(al[tm][0], al[tm][1], al[tm][2], al[tm][3], ad + (G_ALO - G_AHI));
            }
            uint32_t b_off = (uint32_t)((ks * 16 + (lane & 7) + (lane & 8)) * 272 +
                                        (wn * 32 + (lane >> 4) * 8) * 2);
            #pragma unroll
            for (int t2 = 0; t2 < 2; t2++) {
                uint32_t bd = smb + G_BHI + b_off + t2 * 32;
                ldsm4t(bh[t2][0], bh[t2][1], bh[t2][2], bh[t2][3], bd);
                ldsm4t(bl[t2][0], bl[t2][1], bl[t2][2], bl[t2][3], bd + (G_BLO - G_BHI));
            }
            #pragma unroll
            for (int tm = 0; tm < 4; tm++)
                #pragma unroll
                for (int tn = 0; tn < 4; tn++) {
                    uint32_t b0h = bh[tn >> 1][(tn & 1) * 2], b1h = bh[tn >> 1][(tn & 1) * 2 + 1];
                    uint32_t b0l = bl[tn >> 1][(tn & 1) * 2], b1l = bl[tn >> 1][(tn & 1) * 2 + 1];
                    mma_bf16(acc[tm][tn], ah[tm], b0h, b1h);
                    mma_bf16(acc[tm][tn], ah[tm], b0l, b1l);
                    mma_bf16(acc[tm][tn], al[tm], b0h, b1h);
                }
        }
        __syncthreads();
    }

    #pragma unroll
    for (int tm = 0; tm < 4; tm++) {
        int r = row0 + wm * 64 + tm * 16 + (lane >> 2);
        #pragma unroll
        for (int tn = 0; tn < 4; tn++) {
            int c = col0 + wn * 32 + tn * 8 + 2 * (lane & 3);
            float2 bv = *(const float2*)(bias + c);
            *(float2*)(C + (size_t)r * N + c) =
                make_float2(acc[tm][tn][0] + bv.x, acc[tm][tn][1] + bv.y);
            *(float2*)(C + (size_t)(r + 8) * N + c) =
                make_float2(acc[tm][tn][2] + bv.x, acc[tm][tn][3] + bv.y);
        }
    }
}

// ---------------------------------------------------------------------------
// Attention (bf16x3): per (128-row tile i, head h). S = tril(QK^T) then O += S@V.
// S fragments masked + split in registers; O accumulated in registers.
// smem: Q/K/V tiles [128][64] pitch 144B (hi+lo), S [128][128] pitch 272B (hi+lo).
// ---------------------------------------------------------------------------
#define AQ_HI 0
#define AQ_LO 18432
#define AK_HI 36864
#define AK_LO 55296
#define AV_HI 73728
#define AV_LO 92160
#define AS_HI 110592
#define AS_LO 145408
#define A_SMEM 180224

__global__ __launch_bounds__(256, 1)
void attn_tc(const float* __restrict__ kqv, float* __restrict__ att)
{
    extern __shared__ char sm[];
    const uint32_t smb = smem_u32(sm);
    const int tid = threadIdx.x;
    const int w = tid >> 5, lane = tid & 31;
    const int wm = w >> 2, wn = w & 3;
    const int i = 31 - blockIdx.x;          // heavy tiles first
    const int h = blockIdx.y;
    const int row0 = i * 128;
    const int ldg = 3 * D_EMBD;

    const float* qg = kqv + D_EMBD + h * D_HEAD;       // split order: k, q, v
    const float* kg = kqv + h * D_HEAD;
    const float* vg = kqv + 2 * D_EMBD + h * D_HEAD;

    const int t_r = tid >> 4, t_c = (tid & 15) * 4;    // 128x64 tile loads

    // Q tile -> hi/lo smem
    {
        float4 rq[8];
        #pragma unroll
        for (int l = 0; l < 8; l++)
            rq[l] = *(const float4*)(qg + (size_t)(row0 + t_r + l * 16) * ldg + t_c);
        #pragma unroll
        for (int l = 0; l < 8; l++) {
            uint32_t h0, l0, h1, l1;
            split2(rq[l].x, rq[l].y, h0, l0);
            split2(rq[l].z, rq[l].w, h1, l1);
            uint32_t off = (uint32_t)((t_r + l * 16) * 144 + t_c * 2);
            *(uint2*)(sm + AQ_HI + off) = make_uint2(h0, h1);
            *(uint2*)(sm + AQ_LO + off) = make_uint2(l0, l1);
        }
    }

    float oacc[4][2][4];
    #pragma unroll
    for (int a = 0; a < 4; a++)
        #pragma unroll
        for (int b = 0; b < 2; b++)
            #pragma unroll
            for (int cc = 0; cc < 4; cc++) oacc[a][b][cc] = 0.0f;

    for (int j = 0; j <= i; j++) {
        __syncthreads();   // previous O-MMA reads of V/S done before overwrite
        {
            float4 rk[8], rv[8];
            #pragma unroll
            for (int l = 0; l < 8; l++) {
                rk[l] = *(const float4*)(kg + (size_t)(j * 128 + t_r + l * 16) * ldg + t_c);
                rv[l] = *(const float4*)(vg + (size_t)(j * 128 + t_r + l * 16) * ldg + t_c);
            }
            #pragma unroll
            for (int l = 0; l < 8; l++) {
                uint32_t h0, l0, h1, l1;
                uint32_t off = (uint32_t)((t_r + l * 16) * 144 + t_c * 2);
                split2(rk[l].x, rk[l].y, h0, l0);
                split2(rk[l].z, rk[l].w, h1, l1);
                *(uint2*)(sm + AK_HI + off) = make_uint2(h0, h1);
                *(uint2*)(sm + AK_LO + off) = make_uint2(l0, l1);
                split2(rv[l].x, rv[l].y, h0, l0);
                split2(rv[l].z, rv[l].w, h1, l1);
                *(uint2*)(sm + AV_HI + off) = make_uint2(h0, h1);
                *(uint2*)(sm + AV_LO + off) = make_uint2(l0, l1);
            }
        }
        __syncthreads();

        // ---- S = Q @ K^T (warp tile 64x32, kdim 64) ----
        float sacc[4][4][4];
        #pragma unroll
        for (int a = 0; a < 4; a++)
            #pragma unroll
            for (int b = 0; b < 4; b++)
                #pragma unroll
                for (int cc = 0; cc < 4; cc++) sacc[a][b][cc] = 0.0f;

        #pragma unroll
        for (int ks = 0; ks < 4; ks++) {
            uint32_t ah[4][4], al[4][4], bh[2][4], bl[2][4];
            uint32_t a_off = (uint32_t)((wm * 64 + (lane & 15)) * 144 +
                                        (ks * 16 + (lane >> 4) * 8) * 2);
            #pragma unroll
            for (int tm = 0; tm < 4; tm++) {
                uint32_t ad = smb + AQ_HI + a_off + tm * 16 * 144;
                ldsm4(ah[tm][0], ah[tm][1], ah[tm][2], ah[tm][3], ad);
                ldsm4(al[tm][0], al[tm][1], al[tm][2], al[tm][3], ad + (AQ_LO - AQ_HI));
            }
            // K natural [key][d] == col-major B -> non-trans ldmatrix
            uint32_t b_off = (uint32_t)((wn * 32 + (lane & 7) + ((lane >> 1) & 8)) * 144 +
                                        (ks * 16 + (lane & 8)) * 2);
            #pragma unroll
            for (int t2 = 0; t2 < 2; t2++) {
                uint32_t bd = smb + AK_HI + b_off + t2 * 16 * 144;
                ldsm4(bh[t2][0], bh[t2][1], bh[t2][2], bh[t2][3], bd);
                ldsm4(bl[t2][0], bl[t2][1], bl[t2][2], bl[t2][3], bd + (AK_LO - AK_HI));
            }
            #pragma unroll
            for (int tm = 0; tm < 4; tm++)
                #pragma unroll
                for (int tn = 0; tn < 4; tn++) {
                    uint32_t b0h = bh[tn >> 1][(tn & 1) * 2], b1h = bh[tn >> 1][(tn & 1) * 2 + 1];
                    uint32_t b0l = bl[tn >> 1][(tn & 1) * 2], b1l = bl[tn >> 1][(tn & 1) * 2 + 1];
                    mma_bf16(sacc[tm][tn], ah[tm], b0h, b1h);
                    mma_bf16(sacc[tm][tn], ah[tm], b0l, b1l);
                    mma_bf16(sacc[tm][tn], al[tm], b0h, b1h);
                }
        }

        // ---- mask (diag block only) + split S to hi/lo smem ----
        {
            const bool diag = (j == i);
            #pragma unroll
            for (int tm = 0; tm < 4; tm++) {
                int rl = wm * 64 + tm * 16 + (lane >> 2);
                #pragma unroll
                for (int tn = 0; tn < 4; tn++) {
                    int cl = wn * 32 + tn * 8 + 2 * (lane & 3);
                    float c0 = sacc[tm][tn][0], c1 = sacc[tm][tn][1];
                    float c2 = sacc[tm][tn][2], c3 = sacc[tm][tn][3];
                    if (diag) {
                        if (cl     > rl)     c0 = 0.0f;
                        if (cl + 1 > rl)     c1 = 0.0f;
                        if (cl     > rl + 8) c2 = 0.0f;
                        if (cl + 1 > rl + 8) c3 = 0.0f;
                    }
                    uint32_t h0, l0, h1, l1;
                    split2(c0, c1, h0, l0);
                    split2(c2, c3, h1, l1);
                    uint32_t off0 = (uint32_t)(rl * 272 + cl * 2);
                    uint32_t off1 = (uint32_t)((rl + 8) * 272 + cl * 2);
                    *(uint32_t*)(sm + AS_HI + off0) = h0;
                    *(uint32_t*)(sm + AS_LO + off0) = l0;
                    *(uint32_t*)(sm + AS_HI + off1) = h1;
                    *(uint32_t*)(sm + AS_LO + off1) = l1;
                }
            }
        }
        __syncthreads();

        // ---- O += S @ V (warp tile 64x16, kdim 128) ----
        #pragma unroll
        for (int ks = 0; ks < 8; ks++) {
            uint32_t ah[4][4], al[4][4], bh[4], bl[4];
            uint32_t a_off = (uint32_t)((wm * 64 + (lane & 15)) * 272 +
                                        (ks * 16 + (lane >> 4) * 8) * 2);
            #pragma unroll
            for (int tm = 0; tm < 4; tm++) {
                uint32_t ad = smb + AS_HI + a_off + tm * 16 * 272;
                ldsm4(ah[tm][0], ah[tm][1], ah[tm][2], ah[tm][3], ad);
                ldsm4(al[tm][0], al[tm][1], al[tm][2], al[tm][3], ad + (AS_LO - AS_HI));
            }
            uint32_t b_off = (uint32_t)((ks * 16 + (lane & 7) + (lane & 8)) * 144 +
                                        (wn * 16 + (lane >> 4) * 8) * 2);
            ldsm4t(bh[0], bh[1], bh[2], bh[3], smb + AV_HI + b_off);
            ldsm4t(bl[0], bl[1], bl[2], bl[3], smb + AV_LO + b_off);
            #pragma unroll
            for (int tm = 0; tm < 4; tm++)
                #pragma unroll
                for (int tn = 0; tn < 2; tn++) {
                    mma_bf16(oacc[tm][tn], ah[tm], bh[tn * 2], bh[tn * 2 + 1]);
                    mma_bf16(oacc[tm][tn], ah[tm], bl[tn * 2], bl[tn * 2 + 1]);
                    mma_bf16(oacc[tm][tn], al[tm], bh[tn * 2], bh[tn * 2 + 1]);
                }
        }
    }

    // ---- epilogue: O -> att (t, h*d layout) ----
    #pragma unroll
    for (int tm = 0; tm < 4; tm++) {
        int r = row0 + wm * 64 + tm * 16 + (lane >> 2);
        #pragma unroll
        for (int tn = 0; tn < 2; tn++) {
            int c = h * D_HEAD + wn * 16 + tn * 8 + 2 * (lane & 3);
            *(float2*)(att + (size_t)r * D_EMBD + c) =
                make_float2(oacc[tm][tn][0], oacc[tm][tn][1]);
            *(float2*)(att + (size_t)(r + 8) * D_EMBD + c) =
                make_float2(oacc[tm][tn][2], oacc[tm][tn][3]);
        }
    }
}

// ---------------------------------------------------------------------------
extern "C" void kernel_launch(void* const* d_in, const int* in_sizes, int n_in,
                              void* d_out, int out_size)
{
    const float* x  = (const float*)d_in[0];
    const float* W1 = (const float*)d_in[1];
    const float* b1 = (const float*)d_in[2];
    const float* W2 = (const float*)d_in[3];
    const float* b2 = (const float*)d_in[4];
    float* out = (float*)d_out;

    float *kqv, *att;
    cudaGetSymbolAddress((void**)&kqv, g_kqv);
    cudaGetSymbolAddress((void**)&att, g_att);

    cudaFuncSetAttribute(attn_tc, cudaFuncAttributeMaxDynamicSharedMemorySize, A_SMEM);

    gemm_tc<<<dim3(3 * D_EMBD / 128, T_SEQ / 128), 256, G_SMEM>>>(
        x, W1, b1, kqv, T_SEQ, 3 * D_EMBD, D_EMBD);

    attn_tc<<<dim3(T_SEQ / 128, N_HEADS), 256, A_SMEM>>>(kqv, att);

    gemm_tc<<<dim3(D_EMBD / 128, T_SEQ / 128), 256, G_SMEM>>>(
        att, W2, b2, out, T_SEQ, D_EMBD, D_EMBD);
}

// round 4
// speedup vs baseline: 2.6450x; 1.0890x over previous
#include <cuda_runtime.h>
#include <cuda_bf16.h>
#include <cstdint>

#define T_SEQ   4096
#define D_EMBD  1024
#define N_HEADS 16
#define D_HEAD  64

// bf16 hi/lo split scratch (device globals — no runtime allocation allowed)
__device__ __nv_bfloat16 g_xhi[(size_t)T_SEQ * D_EMBD];
__device__ __nv_bfloat16 g_xlo[(size_t)T_SEQ * D_EMBD];
__device__ __nv_bfloat16 g_w1hi[(size_t)D_EMBD * 3 * D_EMBD];
__device__ __nv_bfloat16 g_w1lo[(size_t)D_EMBD * 3 * D_EMBD];
__device__ __nv_bfloat16 g_w2hi[(size_t)D_EMBD * D_EMBD];
__device__ __nv_bfloat16 g_w2lo[(size_t)D_EMBD * D_EMBD];
__device__ __nv_bfloat16 g_kqvhi[(size_t)T_SEQ * 3 * D_EMBD];
__device__ __nv_bfloat16 g_kqvlo[(size_t)T_SEQ * 3 * D_EMBD];
__device__ __nv_bfloat16 g_atthi[(size_t)T_SEQ * D_EMBD];
__device__ __nv_bfloat16 g_attlo[(size_t)T_SEQ * D_EMBD];

// ---------------------------------------------------------------------------
// Helpers
// ---------------------------------------------------------------------------
__device__ __forceinline__ uint32_t smem_u32(const void* p) {
    uint32_t a;
    asm("{ .reg .u64 t; cvta.to.shared.u64 t, %1; cvt.u32.u64 %0, t; }"
        : "=r"(a) : "l"(p));
    return a;
}
__device__ __forceinline__ void ldsm4(uint32_t& r0, uint32_t& r1, uint32_t& r2,
                                      uint32_t& r3, uint32_t addr) {
    asm volatile("ldmatrix.sync.aligned.m8n8.x4.shared.b16 {%0,%1,%2,%3}, [%4];"
                 : "=r"(r0), "=r"(r1), "=r"(r2), "=r"(r3) : "r"(addr));
}
__device__ __forceinline__ void ldsm4t(uint32_t& r0, uint32_t& r1, uint32_t& r2,
                                       uint32_t& r3, uint32_t addr) {
    asm volatile("ldmatrix.sync.aligned.m8n8.x4.trans.shared.b16 {%0,%1,%2,%3}, [%4];"
                 : "=r"(r0), "=r"(r1), "=r"(r2), "=r"(r3) : "r"(addr));
}
__device__ __forceinline__ void mma_bf16(float* c, const uint32_t* a,
                                         uint32_t b0, uint32_t b1) {
    asm volatile(
        "mma.sync.aligned.m16n8k16.row.col.f32.bf16.bf16.f32 "
        "{%0,%1,%2,%3}, {%4,%5,%6,%7}, {%8,%9}, {%0,%1,%2,%3};"
        : "+f"(c[0]), "+f"(c[1]), "+f"(c[2]), "+f"(c[3])
        : "r"(a[0]), "r"(a[1]), "r"(a[2]), "r"(a[3]), "r"(b0), "r"(b1));
}
__device__ __forceinline__ void cpa16(uint32_t dst, const void* src) {
    asm volatile("cp.async.cg.shared.global [%0], [%1], 16;" :: "r"(dst), "l"(src));
}
#define CP_COMMIT() asm volatile("cp.async.commit_group;" ::: "memory")
#define CP_WAIT(n)  asm volatile("cp.async.wait_group %0;" :: "n"(n) : "memory")

__device__ __forceinline__ void split2(float v0, float v1, uint32_t& hi, uint32_t& lo) {
    __nv_bfloat16 h0 = __float2bfloat16(v0), h1 = __float2bfloat16(v1);
    float r0 = v0 - __bfloat162float(h0);
    float r1 = v1 - __bfloat162float(h1);
    __nv_bfloat16 l0 = __float2bfloat16(r0), l1 = __float2bfloat16(r1);
    hi = (uint32_t)__bfloat16_as_ushort(h0) | ((uint32_t)__bfloat16_as_ushort(h1) << 16);
    lo = (uint32_t)__bfloat16_as_ushort(l0) | ((uint32_t)__bfloat16_as_ushort(l1) << 16);
}

// ---------------------------------------------------------------------------
// Prepass: fp32 -> bf16 hi/lo arrays
// ---------------------------------------------------------------------------
__global__ void conv_split(const float* __restrict__ src,
                           __nv_bfloat16* __restrict__ hi,
                           __nv_bfloat16* __restrict__ lo, int n)
{
    int idx = (blockIdx.x * blockDim.x + threadIdx.x) * 4;
    if (idx >= n) return;
    float4 v = *(const float4*)(src + idx);
    uint32_t h0, l0, h1, l1;
    split2(v.x, v.y, h0, l0);
    split2(v.z, v.w, h1, l1);
    *(uint2*)(hi + idx) = make_uint2(h0, h1);
    *(uint2*)(lo + idx) = make_uint2(l0, l1);
}

// ---------------------------------------------------------------------------
// Pipelined bf16x3 GEMM: C = A @ B (+bias). BM=BN=128, BK=32, 4-stage cp.async.
// 8 warps, warp grid 2(m) x 4(n), warp tile 64x32.
// Stage: Ahi 128x80B, Alo, Bhi 32x272B, Blo.
// Output: fp32 (Cf) or bf16 hi/lo pair (Chi/Clo).
// ---------------------------------------------------------------------------
#define SA_HI 0
#define SA_LO 10240
#define SB_HI 20480
#define SB_LO 29184
#define STAGE_SZ 37888
#define G_SMEM (STAGE_SZ * 4)

__global__ __launch_bounds__(256, 1)
void gemm_tc(const __nv_bfloat16* __restrict__ Ahi, const __nv_bfloat16* __restrict__ Alo,
             const __nv_bfloat16* __restrict__ Bhi, const __nv_bfloat16* __restrict__ Blo,
             const float* __restrict__ bias,
             float* __restrict__ Cf,
             __nv_bfloat16* __restrict__ Chi, __nv_bfloat16* __restrict__ Clo,
             int M, int N, int K)
{
    extern __shared__ char sm[];
    const uint32_t smb = smem_u32(sm);
    const int tid = threadIdx.x;
    const int w = tid >> 5, lane = tid & 31;
    const int wm = w >> 2, wn = w & 3;
    const int row0 = blockIdx.y * 128, col0 = blockIdx.x * 128;

    float acc[4][4][4];
    #pragma unroll
    for (int a = 0; a < 4; a++)
        #pragma unroll
        for (int b = 0; b < 4; b++)
            #pragma unroll
            for (int cc = 0; cc < 4; cc++) acc[a][b][cc] = 0.0f;

    const int nchunk = K >> 5;

    // stage issue: per thread 2 pieces of each of Ahi/Alo/Bhi/Blo
    #define G_ISSUE(kc)                                                         \
    do {                                                                        \
        uint32_t base = smb + ((kc) & 3) * STAGE_SZ;                            \
        _Pragma("unroll")                                                       \
        for (int l = 0; l < 2; l++) {                                           \
            int slot = tid + l * 256;                                           \
            int r = slot >> 2, p = slot & 3;                                    \
            size_t ga = (size_t)(row0 + r) * K + (kc) * 32 + p * 8;             \
            cpa16(base + SA_HI + r * 80 + p * 16, Ahi + ga);                    \
            cpa16(base + SA_LO + r * 80 + p * 16, Alo + ga);                    \
            int br = slot >> 4, bp = slot & 15;                                 \
            size_t gb = (size_t)((kc) * 32 + br) * N + col0 + bp * 8;           \
            cpa16(base + SB_HI + br * 272 + bp * 16, Bhi + gb);                 \
            cpa16(base + SB_LO + br * 272 + bp * 16, Blo + gb);                 \
        }                                                                       \
    } while (0)

    for (int s = 0; s < 3; s++) {
        if (s < nchunk) G_ISSUE(s);
        CP_COMMIT();
    }

    for (int kc = 0; kc < nchunk; kc++) {
        CP_WAIT(2);
        __syncthreads();
        int nk = kc + 3;
        if (nk < nchunk) G_ISSUE(nk);
        CP_COMMIT();

        const uint32_t sbase = smb + (kc & 3) * STAGE_SZ;
        #pragma unroll
        for (int ks = 0; ks < 2; ks++) {
            uint32_t ah[4][4], al[4][4], bh[2][4], bl[2][4];
            uint32_t a_off = (uint32_t)((wm * 64 + (lane & 15)) * 80 +
                                        (ks * 16 + (lane >> 4) * 8) * 2);
            #pragma unroll
            for (int tm = 0; tm < 4; tm++) {
                uint32_t ad = sbase + SA_HI + a_off + tm * 16 * 80;
                ldsm4(ah[tm][0], ah[tm][1], ah[tm][2], ah[tm][3], ad);
                ldsm4(al[tm][0], al[tm][1], al[tm][2], al[tm][3], ad + (SA_LO - SA_HI));
            }
            uint32_t b_off = (uint32_t)((ks * 16 + (lane & 7) + (lane & 8)) * 272 +
                                        (wn * 32 + (lane >> 4) * 8) * 2);
            #pragma unroll
            for (int t2 = 0; t2 < 2; t2++) {
                uint32_t bd = sbase + SB_HI + b_off + t2 * 32;
                ldsm4t(bh[t2][0], bh[t2][1], bh[t2][2], bh[t2][3], bd);
                ldsm4t(bl[t2][0], bl[t2][1], bl[t2][2], bl[t2][3], bd + (SB_LO - SB_HI));
            }
            #pragma unroll
            for (int tm = 0; tm < 4; tm++)
                #pragma unroll
                for (int tn = 0; tn < 4; tn++) {
                    uint32_t b0h = bh[tn >> 1][(tn & 1) * 2], b1h = bh[tn >> 1][(tn & 1) * 2 + 1];
                    uint32_t b0l = bl[tn >> 1][(tn & 1) * 2], b1l = bl[tn >> 1][(tn & 1) * 2 + 1];
                    mma_bf16(acc[tm][tn], ah[tm], b0h, b1h);
                    mma_bf16(acc[tm][tn], ah[tm], b0l, b1l);
                    mma_bf16(acc[tm][tn], al[tm], b0h, b1h);
                }
        }
    }

    #pragma unroll
    for (int tm = 0; tm < 4; tm++) {
        int r = row0 + wm * 64 + tm * 16 + (lane >> 2);
        #pragma unroll
        for (int tn = 0; tn < 4; tn++) {
            int c = col0 + wn * 32 + tn * 8 + 2 * (lane & 3);
            float2 bv = *(const float2*)(bias + c);
            float c0 = acc[tm][tn][0] + bv.x, c1 = acc[tm][tn][1] + bv.y;
            float c2 = acc[tm][tn][2] + bv.x, c3 = acc[tm][tn][3] + bv.y;
            if (Cf) {
                *(float2*)(Cf + (size_t)r * N + c) = make_float2(c0, c1);
                *(float2*)(Cf + (size_t)(r + 8) * N + c) = make_float2(c2, c3);
            } else {
                uint32_t h0, l0, h1, l1;
                split2(c0, c1, h0, l0);
                split2(c2, c3, h1, l1);
                *(uint32_t*)(Chi + (size_t)r * N + c) = h0;
                *(uint32_t*)(Clo + (size_t)r * N + c) = l0;
                *(uint32_t*)(Chi + (size_t)(r + 8) * N + c) = h1;
                *(uint32_t*)(Clo + (size_t)(r + 8) * N + c) = l1;
            }
        }
    }
}

// ---------------------------------------------------------------------------
// Attention (bf16x3): per (128-row tile i, head h). S = tril(QK^T), O += S@V.
// Q/K/V arrive pre-split in global bf16; loaded via cp.async.
// smem: Q/K/V tiles [128] rows pitch 144B; S [128] rows pitch 272B (hi+lo).
// ---------------------------------------------------------------------------
#define AQ_HI 0
#define AQ_LO 18432
#define AK_HI 36864
#define AK_LO 55296
#define AV_HI 73728
#define AV_LO 92160
#define AS_HI 110592
#define AS_LO 145408
#define A_SMEM 180224

__global__ __launch_bounds__(256, 1)
void attn_tc(const __nv_bfloat16* __restrict__ kqvhi,
             const __nv_bfloat16* __restrict__ kqvlo,
             __nv_bfloat16* __restrict__ atthi,
             __nv_bfloat16* __restrict__ attlo)
{
    extern __shared__ char sm[];
    const uint32_t smb = smem_u32(sm);
    const int tid = threadIdx.x;
    const int w = tid >> 5, lane = tid & 31;
    const int wm = w >> 2, wn = w & 3;
    const int i = 31 - blockIdx.x;          // heavy tiles first
    const int h = blockIdx.y;
    const int row0 = i * 128;
    const int ldg = 3 * D_EMBD;

    const __nv_bfloat16* qhi = kqvhi + D_EMBD + h * D_HEAD;   // order: k, q, v
    const __nv_bfloat16* qlo = kqvlo + D_EMBD + h * D_HEAD;
    const __nv_bfloat16* khi = kqvhi + h * D_HEAD;
    const __nv_bfloat16* klo = kqvlo + h * D_HEAD;
    const __nv_bfloat16* vhi = kqvhi + 2 * D_EMBD + h * D_HEAD;
    const __nv_bfloat16* vlo = kqvlo + 2 * D_EMBD + h * D_HEAD;

    // Q tile (128 rows x 64 bf16 hi+lo) via cp.async
    #pragma unroll
    for (int l = 0; l < 4; l++) {
        int slot = tid + l * 256;
        int r = slot >> 3, p = slot & 7;
        size_t go = (size_t)(row0 + r) * ldg + p * 8;
        cpa16(smb + AQ_HI + r * 144 + p * 16, qhi + go);
        cpa16(smb + AQ_LO + r * 144 + p * 16, qlo + go);
    }
    CP_COMMIT();

    float oacc[4][2][4];
    #pragma unroll
    for (int a = 0; a < 4; a++)
        #pragma unroll
        for (int b = 0; b < 2; b++)
            #pragma unroll
            for (int cc = 0; cc < 4; cc++) oacc[a][b][cc] = 0.0f;

    for (int j = 0; j <= i; j++) {
        __syncthreads();   // prior O-MMA reads of K/V/S done before overwrite
        #pragma unroll
        for (int l = 0; l < 4; l++) {
            int slot = tid + l * 256;
            int r = slot >> 3, p = slot & 7;
            size_t go = (size_t)(j * 128 + r) * ldg + p * 8;
            uint32_t d = r * 144 + p * 16;
            cpa16(smb + AK_HI + d, khi + go);
            cpa16(smb + AK_LO + d, klo + go);
            cpa16(smb + AV_HI + d, vhi + go);
            cpa16(smb + AV_LO + d, vlo + go);
        }
        CP_COMMIT();
        CP_WAIT(0);
        __syncthreads();

        // ---- S = Q @ K^T (warp tile 64x32, kdim 64) ----
        float sacc[4][4][4];
        #pragma unroll
        for (int a = 0; a < 4; a++)
            #pragma unroll
            for (int b = 0; b < 4; b++)
                #pragma unroll
                for (int cc = 0; cc < 4; cc++) sacc[a][b][cc] = 0.0f;

        #pragma unroll
        for (int ks = 0; ks < 4; ks++) {
            uint32_t ah[4][4], al[4][4], bh[2][4], bl[2][4];
            uint32_t a_off = (uint32_t)((wm * 64 + (lane & 15)) * 144 +
                                        (ks * 16 + (lane >> 4) * 8) * 2);
            #pragma unroll
            for (int tm = 0; tm < 4; tm++) {
                uint32_t ad = smb + AQ_HI + a_off + tm * 16 * 144;
                ldsm4(ah[tm][0], ah[tm][1], ah[tm][2], ah[tm][3], ad);
                ldsm4(al[tm][0], al[tm][1], al[tm][2], al[tm][3], ad + (AQ_LO - AQ_HI));
            }
            // K natural [key][d] == col-major B -> non-trans ldmatrix
            uint32_t b_off = (uint32_t)((wn * 32 + (lane & 7) + ((lane >> 1) & 8)) * 144 +
                                        (ks * 16 + (lane & 8)) * 2);
            #pragma unroll
            for (int t2 = 0; t2 < 2; t2++) {
                uint32_t bd = smb + AK_HI + b_off + t2 * 16 * 144;
                ldsm4(bh[t2][0], bh[t2][1], bh[t2][2], bh[t2][3], bd);
                ldsm4(bl[t2][0], bl[t2][1], bl[t2][2], bl[t2][3], bd + (AK_LO - AK_HI));
            }
            #pragma unroll
            for (int tm = 0; tm < 4; tm++)
                #pragma unroll
                for (int tn = 0; tn < 4; tn++) {
                    uint32_t b0h = bh[tn >> 1][(tn & 1) * 2], b1h = bh[tn >> 1][(tn & 1) * 2 + 1];
                    uint32_t b0l = bl[tn >> 1][(tn & 1) * 2], b1l = bl[tn >> 1][(tn & 1) * 2 + 1];
                    mma_bf16(sacc[tm][tn], ah[tm], b0h, b1h);
                    mma_bf16(sacc[tm][tn], ah[tm], b0l, b1l);
                    mma_bf16(sacc[tm][tn], al[tm], b0h, b1h);
                }
        }

        // ---- mask (diag block only) + split S to hi/lo smem ----
        {
            const bool diag = (j == i);
            #pragma unroll
            for (int tm = 0; tm < 4; tm++) {
                int rl = wm * 64 + tm * 16 + (lane >> 2);
                #pragma unroll
                for (int tn = 0; tn < 4; tn++) {
                    int cl = wn * 32 + tn * 8 + 2 * (lane & 3);
                    float c0 = sacc[tm][tn][0], c1 = sacc[tm][tn][1];
                    float c2 = sacc[tm][tn][2], c3 = sacc[tm][tn][3];
                    if (diag) {
                        if (cl     > rl)     c0 = 0.0f;
                        if (cl + 1 > rl)     c1 = 0.0f;
                        if (cl     > rl + 8) c2 = 0.0f;
                        if (cl + 1 > rl + 8) c3 = 0.0f;
                    }
                    uint32_t h0, l0, h1, l1;
                    split2(c0, c1, h0, l0);
                    split2(c2, c3, h1, l1);
                    uint32_t off0 = (uint32_t)(rl * 272 + cl * 2);
                    uint32_t off1 = (uint32_t)((rl + 8) * 272 + cl * 2);
                    *(uint32_t*)(sm + AS_HI + off0) = h0;
                    *(uint32_t*)(sm + AS_LO + off0) = l0;
                    *(uint32_t*)(sm + AS_HI + off1) = h1;
                    *(uint32_t*)(sm + AS_LO + off1) = l1;
                }
            }
        }
        __syncthreads();

        // ---- O += S @ V (warp tile 64x16, kdim 128) ----
        #pragma unroll
        for (int ks = 0; ks < 8; ks++) {
            uint32_t ah[4][4], al[4][4], bh[4], bl[4];
            uint32_t a_off = (uint32_t)((wm * 64 + (lane & 15)) * 272 +
                                        (ks * 16 + (lane >> 4) * 8) * 2);
            #pragma unroll
            for (int tm = 0; tm < 4; tm++) {
                uint32_t ad = smb + AS_HI + a_off + tm * 16 * 272;
                ldsm4(ah[tm][0], ah[tm][1], ah[tm][2], ah[tm][3], ad);
                ldsm4(al[tm][0], al[tm][1], al[tm][2], al[tm][3], ad + (AS_LO - AS_HI));
            }
            uint32_t b_off = (uint32_t)((ks * 16 + (lane & 7) + (lane & 8)) * 144 +
                                        (wn * 16 + (lane >> 4) * 8) * 2);
            ldsm4t(bh[0], bh[1], bh[2], bh[3], smb + AV_HI + b_off);
            ldsm4t(bl[0], bl[1], bl[2], bl[3], smb + AV_LO + b_off);
            #pragma unroll
            for (int tm = 0; tm < 4; tm++)
                #pragma unroll
                for (int tn = 0; tn < 2; tn++) {
                    mma_bf16(oacc[tm][tn], ah[tm], bh[tn * 2], bh[tn * 2 + 1]);
                    mma_bf16(oacc[tm][tn], ah[tm], bl[tn * 2], bl[tn * 2 + 1]);
                    mma_bf16(oacc[tm][tn], al[tm], bh[tn * 2], bh[tn * 2 + 1]);
                }
        }
    }

    // ---- epilogue: O -> att hi/lo (t, h*d layout) ----
    #pragma unroll
    for (int tm = 0; tm < 4; tm++) {
        int r = row0 + wm * 64 + tm * 16 + (lane >> 2);
        #pragma unroll
        for (int tn = 0; tn < 2; tn++) {
            int c = h * D_HEAD + wn * 16 + tn * 8 + 2 * (lane & 3);
            uint32_t h0, l0, h1, l1;
            split2(oacc[tm][tn][0], oacc[tm][tn][1], h0, l0);
            split2(oacc[tm][tn][2], oacc[tm][tn][3], h1, l1);
            *(uint32_t*)(atthi + (size_t)r * D_EMBD + c) = h0;
            *(uint32_t*)(attlo + (size_t)r * D_EMBD + c) = l0;
            *(uint32_t*)(atthi + (size_t)(r + 8) * D_EMBD + c) = h1;
            *(uint32_t*)(attlo + (size_t)(r + 8) * D_EMBD + c) = l1;
        }
    }
}

// ---------------------------------------------------------------------------
extern "C" void kernel_launch(void* const* d_in, const int* in_sizes, int n_in,
                              void* d_out, int out_size)
{
    const float* x  = (const float*)d_in[0];
    const float* W1 = (const float*)d_in[1];
    const float* b1 = (const float*)d_in[2];
    const float* W2 = (const float*)d_in[3];
    const float* b2 = (const float*)d_in[4];
    float* out = (float*)d_out;

    __nv_bfloat16 *xhi, *xlo, *w1hi, *w1lo, *w2hi, *w2lo, *kqvhi, *kqvlo, *atthi, *attlo;
    cudaGetSymbolAddress((void**)&xhi, g_xhi);
    cudaGetSymbolAddress((void**)&xlo, g_xlo);
    cudaGetSymbolAddress((void**)&w1hi, g_w1hi);
    cudaGetSymbolAddress((void**)&w1lo, g_w1lo);
    cudaGetSymbolAddress((void**)&w2hi, g_w2hi);
    cudaGetSymbolAddress((void**)&w2lo, g_w2lo);
    cudaGetSymbolAddress((void**)&kqvhi, g_kqvhi);
    cudaGetSymbolAddress((void**)&kqvlo, g_kqvlo);
    cudaGetSymbolAddress((void**)&atthi, g_atthi);
    cudaGetSymbolAddress((void**)&attlo, g_attlo);

    cudaFuncSetAttribute(gemm_tc, cudaFuncAttributeMaxDynamicSharedMemorySize, G_SMEM);
    cudaFuncSetAttribute(attn_tc, cudaFuncAttributeMaxDynamicSharedMemorySize, A_SMEM);

    int nx = T_SEQ * D_EMBD, nw1 = D_EMBD * 3 * D_EMBD, nw2 = D_EMBD * D_EMBD;
    conv_split<<<nx / 1024, 256>>>(x, xhi, xlo, nx);
    conv_split<<<nw1 / 1024, 256>>>(W1, w1hi, w1lo, nw1);
    conv_split<<<nw2 / 1024, 256>>>(W2, w2hi, w2lo, nw2);

    gemm_tc<<<dim3(3 * D_EMBD / 128, T_SEQ / 128), 256, G_SMEM>>>(
        xhi, xlo, w1hi, w1lo, b1, nullptr, kqvhi, kqvlo,
        T_SEQ, 3 * D_EMBD, D_EMBD);

    attn_tc<<<dim3(T_SEQ / 128, N_HEADS), 256, A_SMEM>>>(kqvhi, kqvlo, atthi, attlo);

    gemm_tc<<<dim3(D_EMBD / 128, T_SEQ / 128), 256, G_SMEM>>>(
        atthi, attlo, w2hi, w2lo, b2, out, nullptr, nullptr,
        T_SEQ, D_EMBD, D_EMBD);
}

// round 5
// speedup vs baseline: 2.8942x; 1.0942x over previous
#include <cuda_runtime.h>
#include <cuda_bf16.h>
#include <cstdint>

#define T_SEQ   4096
#define D_EMBD  1024
#define N_HEADS 16
#define D_HEAD  64

// bf16 hi/lo split scratch (device globals — no runtime allocation allowed)
__device__ __nv_bfloat16 g_xhi[(size_t)T_SEQ * D_EMBD];
__device__ __nv_bfloat16 g_xlo[(size_t)T_SEQ * D_EMBD];
__device__ __nv_bfloat16 g_w1hi[(size_t)D_EMBD * 3 * D_EMBD];
__device__ __nv_bfloat16 g_w1lo[(size_t)D_EMBD * 3 * D_EMBD];
__device__ __nv_bfloat16 g_w2hi[(size_t)D_EMBD * D_EMBD];
__device__ __nv_bfloat16 g_w2lo[(size_t)D_EMBD * D_EMBD];
__device__ __nv_bfloat16 g_kqvhi[(size_t)T_SEQ * 3 * D_EMBD];
__device__ __nv_bfloat16 g_kqvlo[(size_t)T_SEQ * 3 * D_EMBD];
__device__ __nv_bfloat16 g_atthi[(size_t)T_SEQ * D_EMBD];
__device__ __nv_bfloat16 g_attlo[(size_t)T_SEQ * D_EMBD];

// ---------------------------------------------------------------------------
// Helpers
// ---------------------------------------------------------------------------
__device__ __forceinline__ uint32_t smem_u32(const void* p) {
    uint32_t a;
    asm("{ .reg .u64 t; cvta.to.shared.u64 t, %1; cvt.u32.u64 %0, t; }"
        : "=r"(a) : "l"(p));
    return a;
}
__device__ __forceinline__ void ldsm4(uint32_t& r0, uint32_t& r1, uint32_t& r2,
                                      uint32_t& r3, uint32_t addr) {
    asm volatile("ldmatrix.sync.aligned.m8n8.x4.shared.b16 {%0,%1,%2,%3}, [%4];"
                 : "=r"(r0), "=r"(r1), "=r"(r2), "=r"(r3) : "r"(addr));
}
__device__ __forceinline__ void ldsm4t(uint32_t& r0, uint32_t& r1, uint32_t& r2,
                                       uint32_t& r3, uint32_t addr) {
    asm volatile("ldmatrix.sync.aligned.m8n8.x4.trans.shared.b16 {%0,%1,%2,%3}, [%4];"
                 : "=r"(r0), "=r"(r1), "=r"(r2), "=r"(r3) : "r"(addr));
}
__device__ __forceinline__ void mma_bf16(float* c, const uint32_t* a,
                                         uint32_t b0, uint32_t b1) {
    asm volatile(
        "mma.sync.aligned.m16n8k16.row.col.f32.bf16.bf16.f32 "
        "{%0,%1,%2,%3}, {%4,%5,%6,%7}, {%8,%9}, {%0,%1,%2,%3};"
        : "+f"(c[0]), "+f"(c[1]), "+f"(c[2]), "+f"(c[3])
        : "r"(a[0]), "r"(a[1]), "r"(a[2]), "r"(a[3]), "r"(b0), "r"(b1));
}
__device__ __forceinline__ void cpa16(uint32_t dst, const void* src) {
    asm volatile("cp.async.cg.shared.global [%0], [%1], 16;" :: "r"(dst), "l"(src));
}
#define CP_COMMIT() asm volatile("cp.async.commit_group;" ::: "memory")
#define CP_WAIT(n)  asm volatile("cp.async.wait_group %0;" :: "n"(n) : "memory")

__device__ __forceinline__ void split2(float v0, float v1, uint32_t& hi, uint32_t& lo) {
    __nv_bfloat16 h0 = __float2bfloat16(v0), h1 = __float2bfloat16(v1);
    float r0 = v0 - __bfloat162float(h0);
    float r1 = v1 - __bfloat162float(h1);
    __nv_bfloat16 l0 = __float2bfloat16(r0), l1 = __float2bfloat16(r1);
    hi = (uint32_t)__bfloat16_as_ushort(h0) | ((uint32_t)__bfloat16_as_ushort(h1) << 16);
    lo = (uint32_t)__bfloat16_as_ushort(l0) | ((uint32_t)__bfloat16_as_ushort(l1) << 16);
}

// ---------------------------------------------------------------------------
// Prepass: fp32 -> bf16 hi/lo arrays
// ---------------------------------------------------------------------------
__global__ void conv_split(const float* __restrict__ src,
                           __nv_bfloat16* __restrict__ hi,
                           __nv_bfloat16* __restrict__ lo, int n)
{
    int idx = (blockIdx.x * blockDim.x + threadIdx.x) * 4;
    if (idx >= n) return;
    float4 v = *(const float4*)(src + idx);
    uint32_t h0, l0, h1, l1;
    split2(v.x, v.y, h0, l0);
    split2(v.z, v.w, h1, l1);
    *(uint2*)(hi + idx) = make_uint2(h0, h1);
    *(uint2*)(lo + idx) = make_uint2(l0, l1);
}

// ---------------------------------------------------------------------------
// Pipelined bf16x3 GEMM. BM=BN=128, BK=32, 3-stage cp.async, 2 CTAs/SM.
// Swizzled zero-pad smem: A rows 64B (4 quads, q^=(r>>1)&3),
//                         B rows 256B (16 quads, q^=r&7).
// ---------------------------------------------------------------------------
#define SA_HI 0
#define SA_LO 8192
#define SB_HI 16384
#define SB_LO 24576
#define STAGE_SZ 32768
#define G_SMEM (STAGE_SZ * 3)

__global__ __launch_bounds__(256, 2)
void gemm_tc(const __nv_bfloat16* __restrict__ Ahi, const __nv_bfloat16* __restrict__ Alo,
             const __nv_bfloat16* __restrict__ Bhi, const __nv_bfloat16* __restrict__ Blo,
             const float* __restrict__ bias,
             float* __restrict__ Cf,
             __nv_bfloat16* __restrict__ Chi, __nv_bfloat16* __restrict__ Clo,
             int M, int N, int K)
{
    extern __shared__ char sm[];
    const uint32_t smb = smem_u32(sm);
    const int tid = threadIdx.x;
    const int w = tid >> 5, lane = tid & 31;
    const int wm = w >> 2, wn = w & 3;
    const int row0 = blockIdx.y * 128, col0 = blockIdx.x * 128;

    float acc[4][4][4];
    #pragma unroll
    for (int a = 0; a < 4; a++)
        #pragma unroll
        for (int b = 0; b < 4; b++)
            #pragma unroll
            for (int cc = 0; cc < 4; cc++) acc[a][b][cc] = 0.0f;

    const int nchunk = K >> 5;

    #define G_ISSUE(kc)                                                         \
    do {                                                                        \
        uint32_t base = smb + ((kc) % 3) * STAGE_SZ;                            \
        _Pragma("unroll")                                                       \
        for (int l = 0; l < 2; l++) {                                           \
            int slot = tid + l * 256;                                           \
            int ar = slot >> 2, aq = slot & 3;                                  \
            uint32_t aoff = (uint32_t)(ar * 64 + ((aq ^ ((ar >> 1) & 3)) << 4));\
            size_t ga = (size_t)(row0 + ar) * K + (kc) * 32 + aq * 8;           \
            cpa16(base + SA_HI + aoff, Ahi + ga);                               \
            cpa16(base + SA_LO + aoff, Alo + ga);                               \
            int br = slot >> 4, bq = slot & 15;                                 \
            uint32_t boff = (uint32_t)(br * 256 + ((bq ^ (br & 7)) << 4));      \
            size_t gb = (size_t)((kc) * 32 + br) * N + col0 + bq * 8;           \
            cpa16(base + SB_HI + boff, Bhi + gb);                               \
            cpa16(base + SB_LO + boff, Blo + gb);                               \
        }                                                                       \
    } while (0)

    G_ISSUE(0); CP_COMMIT();
    G_ISSUE(1); CP_COMMIT();

    for (int kc = 0; kc < nchunk; kc++) {
        CP_WAIT(1);
        __syncthreads();
        if (kc + 2 < nchunk) G_ISSUE(kc + 2);
        CP_COMMIT();

        const uint32_t sbase = smb + (kc % 3) * STAGE_SZ;
        const int arow = wm * 64 + (lane & 15);
        #pragma unroll
        for (int ks = 0; ks < 2; ks++) {
            uint32_t ah[4][4], al[4][4], bh[2][4], bl[2][4];
            const int aq = ks * 2 + (lane >> 4);
            const uint32_t aswz = (uint32_t)((aq ^ ((arow >> 1) & 3)) << 4);
            #pragma unroll
            for (int tm = 0; tm < 4; tm++) {
                uint32_t ad = sbase + (uint32_t)((arow + tm * 16) * 64) + aswz;
                ldsm4(ah[tm][0], ah[tm][1], ah[tm][2], ah[tm][3], ad + SA_HI);
                ldsm4(al[tm][0], al[tm][1], al[tm][2], al[tm][3], ad + SA_LO);
            }
            const int brow = ks * 16 + (lane & 7) + (lane & 8);
            #pragma unroll
            for (int t2 = 0; t2 < 2; t2++) {
                int bq = wn * 4 + (lane >> 4) + t2 * 2;
                uint32_t bd = sbase + (uint32_t)(brow * 256 + ((bq ^ (lane & 7)) << 4));
                ldsm4t(bh[t2][0], bh[t2][1], bh[t2][2], bh[t2][3], bd + SB_HI);
                ldsm4t(bl[t2][0], bl[t2][1], bl[t2][2], bl[t2][3], bd + SB_LO);
            }
            #pragma unroll
            for (int tm = 0; tm < 4; tm++)
                #pragma unroll
                for (int tn = 0; tn < 4; tn++) {
                    uint32_t b0h = bh[tn >> 1][(tn & 1) * 2], b1h = bh[tn >> 1][(tn & 1) * 2 + 1];
                    uint32_t b0l = bl[tn >> 1][(tn & 1) * 2], b1l = bl[tn >> 1][(tn & 1) * 2 + 1];
                    mma_bf16(acc[tm][tn], ah[tm], b0h, b1h);
                    mma_bf16(acc[tm][tn], ah[tm], b0l, b1l);
                    mma_bf16(acc[tm][tn], al[tm], b0h, b1h);
                }
        }
    }

    #pragma unroll
    for (int tm = 0; tm < 4; tm++) {
        int r = row0 + wm * 64 + tm * 16 + (lane >> 2);
        #pragma unroll
        for (int tn = 0; tn < 4; tn++) {
            int c = col0 + wn * 32 + tn * 8 + 2 * (lane & 3);
            float2 bv = *(const float2*)(bias + c);
            float c0 = acc[tm][tn][0] + bv.x, c1 = acc[tm][tn][1] + bv.y;
            float c2 = acc[tm][tn][2] + bv.x, c3 = acc[tm][tn][3] + bv.y;
            if (Cf) {
                *(float2*)(Cf + (size_t)r * N + c) = make_float2(c0, c1);
                *(float2*)(Cf + (size_t)(r + 8) * N + c) = make_float2(c2, c3);
            } else {
                uint32_t h0, l0, h1, l1;
                split2(c0, c1, h0, l0);
                split2(c2, c3, h1, l1);
                *(uint32_t*)(Chi + (size_t)r * N + c) = h0;
                *(uint32_t*)(Clo + (size_t)r * N + c) = l0;
                *(uint32_t*)(Chi + (size_t)(r + 8) * N + c) = h1;
                *(uint32_t*)(Clo + (size_t)(r + 8) * N + c) = l1;
            }
        }
    }
}

// ---------------------------------------------------------------------------
// Attention (bf16x3): per (128-row tile i, head h). S = tril(QK^T), O += S@V.
// Swizzled tiles (rows 128B, q^=r&7), S rows 256B (q^=(r&7)<<1).
// Double-buffered K/V via cp.async prefetch.
// ---------------------------------------------------------------------------
#define AQ_HI 0
#define AQ_LO 16384
#define AKV(buf) (32768 + (buf) * 65536)   // +0 Khi, +16K Klo, +32K Vhi, +48K Vlo
#define AS_HI 163840
#define AS_LO 196608
#define A_SMEM 229376

__global__ __launch_bounds__(256, 1)
void attn_tc(const __nv_bfloat16* __restrict__ kqvhi,
             const __nv_bfloat16* __restrict__ kqvlo,
             __nv_bfloat16* __restrict__ atthi,
             __nv_bfloat16* __restrict__ attlo)
{
    extern __shared__ char sm[];
    const uint32_t smb = smem_u32(sm);
    const int tid = threadIdx.x;
    const int w = tid >> 5, lane = tid & 31;
    const int wm = w >> 2, wn = w & 3;
    const int i = 31 - blockIdx.x;          // heavy tiles first
    const int h = blockIdx.y;
    const int row0 = i * 128;
    const int ldg = 3 * D_EMBD;

    const __nv_bfloat16* qhi = kqvhi + D_EMBD + h * D_HEAD;   // order: k, q, v
    const __nv_bfloat16* qlo = kqvlo + D_EMBD + h * D_HEAD;
    const __nv_bfloat16* khi = kqvhi + h * D_HEAD;
    const __nv_bfloat16* klo = kqvlo + h * D_HEAD;
    const __nv_bfloat16* vhi = kqvhi + 2 * D_EMBD + h * D_HEAD;
    const __nv_bfloat16* vlo = kqvlo + 2 * D_EMBD + h * D_HEAD;

    // tile loader: r = slot>>3 (0..127), q = slot&7; row pitch 128B, swizzled
    #define KV_ISSUE(jblk, buf)                                                 \
    do {                                                                        \
        uint32_t kb = smb + AKV(buf);                                           \
        _Pragma("unroll")                                                       \
        for (int l = 0; l < 4; l++) {                                           \
            int slot = tid + l * 256;                                           \
            int r = slot >> 3, q = slot & 7;                                    \
            uint32_t d = (uint32_t)(r * 128 + ((q ^ (r & 7)) << 4));            \
            size_t go = (size_t)((jblk) * 128 + r) * ldg + q * 8;               \
            cpa16(kb + d, khi + go);                                            \
            cpa16(kb + 16384 + d, klo + go);                                    \
            cpa16(kb + 32768 + d, vhi + go);                                    \
            cpa16(kb + 49152 + d, vlo + go);                                    \
        }                                                                       \
    } while (0)

    // Q tile
    #pragma unroll
    for (int l = 0; l < 4; l++) {
        int slot = tid + l * 256;
        int r = slot >> 3, q = slot & 7;
        uint32_t d = (uint32_t)(r * 128 + ((q ^ (r & 7)) << 4));
        size_t go = (size_t)(row0 + r) * ldg + q * 8;
        cpa16(smb + AQ_HI + d, qhi + go);
        cpa16(smb + AQ_LO + d, qlo + go);
    }
    KV_ISSUE(0, 0);
    CP_COMMIT();

    float oacc[4][2][4];
    #pragma unroll
    for (int a = 0; a < 4; a++)
        #pragma unroll
        for (int b = 0; b < 2; b++)
            #pragma unroll
            for (int cc = 0; cc < 4; cc++) oacc[a][b][cc] = 0.0f;

    for (int j = 0; j <= i; j++) {
        CP_WAIT(0);
        __syncthreads();
        if (j < i) { KV_ISSUE(j + 1, (j + 1) & 1); CP_COMMIT(); }

        const uint32_t kvb = smb + AKV(j & 1);

        // ---- S = Q @ K^T (warp tile 64x32, kdim 64) ----
        float sacc[4][4][4];
        #pragma unroll
        for (int a = 0; a < 4; a++)
            #pragma unroll
            for (int b = 0; b < 4; b++)
                #pragma unroll
                for (int cc = 0; cc < 4; cc++) sacc[a][b][cc] = 0.0f;

        const int arow = wm * 64 + (lane & 15);
        #pragma unroll
        for (int ks = 0; ks < 4; ks++) {
            uint32_t ah[4][4], al[4][4], bh[2][4], bl[2][4];
            const int aq = ks * 2 + (lane >> 4);
            const uint32_t aswz = (uint32_t)((aq ^ (arow & 7)) << 4);
            #pragma unroll
            for (int tm = 0; tm < 4; tm++) {
                uint32_t ad = smb + (uint32_t)((arow + tm * 16) * 128) + aswz;
                ldsm4(ah[tm][0], ah[tm][1], ah[tm][2], ah[tm][3], ad + AQ_HI);
                ldsm4(al[tm][0], al[tm][1], al[tm][2], al[tm][3], ad + AQ_LO);
            }
            const int krow0 = wn * 32 + (lane & 7) + ((lane >> 1) & 8);
            const int kq = ks * 2 + ((lane >> 3) & 1);
            const uint32_t kswz = (uint32_t)((kq ^ (lane & 7)) << 4);
            #pragma unroll
            for (int t2 = 0; t2 < 2; t2++) {
                uint32_t bd = kvb + (uint32_t)((krow0 + t2 * 16) * 128) + kswz;
                ldsm4(bh[t2][0], bh[t2][1], bh[t2][2], bh[t2][3], bd);
                ldsm4(bl[t2][0], bl[t2][1], bl[t2][2], bl[t2][3], bd + 16384);
            }
            #pragma unroll
            for (int tm = 0; tm < 4; tm++)
                #pragma unroll
                for (int tn = 0; tn < 4; tn++) {
                    uint32_t b0h = bh[tn >> 1][(tn & 1) * 2], b1h = bh[tn >> 1][(tn & 1) * 2 + 1];
                    uint32_t b0l = bl[tn >> 1][(tn & 1) * 2], b1l = bl[tn >> 1][(tn & 1) * 2 + 1];
                    mma_bf16(sacc[tm][tn], ah[tm], b0h, b1h);
                    mma_bf16(sacc[tm][tn], ah[tm], b0l, b1l);
                    mma_bf16(sacc[tm][tn], al[tm], b0h, b1h);
                }
        }

        // ---- mask (diag block only) + split S to hi/lo smem ----
        {
            const bool diag = (j == i);
            #pragma unroll
            for (int tm = 0; tm < 4; tm++) {
                int rl = wm * 64 + tm * 16 + (lane >> 2);
                const uint32_t rsw = (uint32_t)((rl & 7) << 1);
                #pragma unroll
                for (int tn = 0; tn < 4; tn++) {
                    int cl = wn * 32 + tn * 8 + 2 * (lane & 3);
                    float c0 = sacc[tm][tn][0], c1 = sacc[tm][tn][1];
                    float c2 = sacc[tm][tn][2], c3 = sacc[tm][tn][3];
                    if (diag) {
                        if (cl     > rl)     c0 = 0.0f;
                        if (cl + 1 > rl)     c1 = 0.0f;
                        if (cl     > rl + 8) c2 = 0.0f;
                        if (cl + 1 > rl + 8) c3 = 0.0f;
                    }
                    uint32_t h0, l0, h1, l1;
                    split2(c0, c1, h0, l0);
                    split2(c2, c3, h1, l1);
                    int q = wn * 4 + tn;
                    uint32_t off0 = (uint32_t)(rl * 256 + ((q ^ rsw) << 4) + 4 * (lane & 3));
                    uint32_t off1 = (uint32_t)((rl + 8) * 256 + ((q ^ rsw) << 4) + 4 * (lane & 3));
                    *(uint32_t*)(sm + AS_HI + off0) = h0;
                    *(uint32_t*)(sm + AS_LO + off0) = l0;
                    *(uint32_t*)(sm + AS_HI + off1) = h1;
                    *(uint32_t*)(sm + AS_LO + off1) = l1;
                }
            }
        }
        __syncthreads();

        // ---- O += S @ V (warp tile 64x16, kdim 128) ----
        #pragma unroll
        for (int ks = 0; ks < 8; ks++) {
            uint32_t ah[4][4], al[4][4], bh[4], bl[4];
            const int aq = ks * 2 + (lane >> 4);
            const uint32_t aswz = (uint32_t)((aq ^ ((lane & 7) << 1)) << 4);
            #pragma unroll
            for (int tm = 0; tm < 4; tm++) {
                uint32_t ad = smb + (uint32_t)((arow + tm * 16) * 256) + aswz;
                ldsm4(ah[tm][0], ah[tm][1], ah[tm][2], ah[tm][3], ad + AS_HI);
                ldsm4(al[tm][0], al[tm][1], al[tm][2], al[tm][3], ad + AS_LO);
            }
            const int vrow = ks * 16 + (lane & 7) + (lane & 8);
            const int vq = wn * 2 + (lane >> 4);
            uint32_t bd = kvb + 32768 +
                          (uint32_t)(vrow * 128 + ((vq ^ (lane & 7)) << 4));
            ldsm4t(bh[0], bh[1], bh[2], bh[3], bd);
            ldsm4t(bl[0], bl[1], bl[2], bl[3], bd + 16384);
            #pragma unroll
            for (int tm = 0; tm < 4; tm++)
                #pragma unroll
                for (int tn = 0; tn < 2; tn++) {
                    mma_bf16(oacc[tm][tn], ah[tm], bh[tn * 2], bh[tn * 2 + 1]);
                    mma_bf16(oacc[tm][tn], ah[tm], bl[tn * 2], bl[tn * 2 + 1]);
                    mma_bf16(oacc[tm][tn], al[tm], bh[tn * 2], bh[tn * 2 + 1]);
                }
        }
    }

    // ---- epilogue: O -> att hi/lo (t, h*d layout) ----
    #pragma unroll
    for (int tm = 0; tm < 4; tm++) {
        int r = row0 + wm * 64 + tm * 16 + (lane >> 2);
        #pragma unroll
        for (int tn = 0; tn < 2; tn++) {
            int c = h * D_HEAD + wn * 16 + tn * 8 + 2 * (lane & 3);
            uint32_t h0, l0, h1, l1;
            split2(oacc[tm][tn][0], oacc[tm][tn][1], h0, l0);
            split2(oacc[tm][tn][2], oacc[tm][tn][3], h1, l1);
            *(uint32_t*)(atthi + (size_t)r * D_EMBD + c) = h0;
            *(uint32_t*)(attlo + (size_t)r * D_EMBD + c) = l0;
            *(uint32_t*)(atthi + (size_t)(r + 8) * D_EMBD + c) = h1;
            *(uint32_t*)(attlo + (size_t)(r + 8) * D_EMBD + c) = l1;
        }
    }
}

// ---------------------------------------------------------------------------
extern "C" void kernel_launch(void* const* d_in, const int* in_sizes, int n_in,
                              void* d_out, int out_size)
{
    const float* x  = (const float*)d_in[0];
    const float* W1 = (const float*)d_in[1];
    const float* b1 = (const float*)d_in[2];
    const float* W2 = (const float*)d_in[3];
    const float* b2 = (const float*)d_in[4];
    float* out = (float*)d_out;

    __nv_bfloat16 *xhi, *xlo, *w1hi, *w1lo, *w2hi, *w2lo, *kqvhi, *kqvlo, *atthi, *attlo;
    cudaGetSymbolAddress((void**)&xhi, g_xhi);
    cudaGetSymbolAddress((void**)&xlo, g_xlo);
    cudaGetSymbolAddress((void**)&w1hi, g_w1hi);
    cudaGetSymbolAddress((void**)&w1lo, g_w1lo);
    cudaGetSymbolAddress((void**)&w2hi, g_w2hi);
    cudaGetSymbolAddress((void**)&w2lo, g_w2lo);
    cudaGetSymbolAddress((void**)&kqvhi, g_kqvhi);
    cudaGetSymbolAddress((void**)&kqvlo, g_kqvlo);
    cudaGetSymbolAddress((void**)&atthi, g_atthi);
    cudaGetSymbolAddress((void**)&attlo, g_attlo);

    cudaFuncSetAttribute(gemm_tc, cudaFuncAttributeMaxDynamicSharedMemorySize, G_SMEM);
    cudaFuncSetAttribute(attn_tc, cudaFuncAttributeMaxDynamicSharedMemorySize, A_SMEM);

    int nx = T_SEQ * D_EMBD, nw1 = D_EMBD * 3 * D_EMBD, nw2 = D_EMBD * D_EMBD;
    conv_split<<<nx / 1024, 256>>>(x, xhi, xlo, nx);
    conv_split<<<nw1 / 1024, 256>>>(W1, w1hi, w1lo, nw1);
    conv_split<<<nw2 / 1024, 256>>>(W2, w2hi, w2lo, nw2);

    gemm_tc<<<dim3(3 * D_EMBD / 128, T_SEQ / 128), 256, G_SMEM>>>(
        xhi, xlo, w1hi, w1lo, b1, nullptr, kqvhi, kqvlo,
        T_SEQ, 3 * D_EMBD, D_EMBD);

    attn_tc<<<dim3(T_SEQ / 128, N_HEADS), 256, A_SMEM>>>(kqvhi, kqvlo, atthi, attlo);

    gemm_tc<<<dim3(D_EMBD / 128, T_SEQ / 128), 256, G_SMEM>>>(
        atthi, attlo, w2hi, w2lo, b2, out, nullptr, nullptr,
        T_SEQ, D_EMBD, D_EMBD);
}

// round 6
// speedup vs baseline: 2.9154x; 1.0073x over previous
#include <cuda_runtime.h>
#include <cuda_bf16.h>
#include <cstdint>

#define T_SEQ   4096
#define D_EMBD  1024
#define N_HEADS 16
#define D_HEAD  64

// bf16 hi/lo split scratch (device globals — no runtime allocation allowed)
__device__ __nv_bfloat16 g_xhi[(size_t)T_SEQ * D_EMBD];
__device__ __nv_bfloat16 g_xlo[(size_t)T_SEQ * D_EMBD];
__device__ __nv_bfloat16 g_w1hi[(size_t)D_EMBD * 3 * D_EMBD];
__device__ __nv_bfloat16 g_w1lo[(size_t)D_EMBD * 3 * D_EMBD];
__device__ __nv_bfloat16 g_w2hi[(size_t)D_EMBD * D_EMBD];
__device__ __nv_bfloat16 g_w2lo[(size_t)D_EMBD * D_EMBD];
__device__ __nv_bfloat16 g_kqvhi[(size_t)T_SEQ * 3 * D_EMBD];
__device__ __nv_bfloat16 g_kqvlo[(size_t)T_SEQ * 3 * D_EMBD];
__device__ __nv_bfloat16 g_atthi[(size_t)T_SEQ * D_EMBD];
__device__ __nv_bfloat16 g_attlo[(size_t)T_SEQ * D_EMBD];

// ---------------------------------------------------------------------------
// Helpers
// ---------------------------------------------------------------------------
__device__ __forceinline__ uint32_t smem_u32(const void* p) {
    uint32_t a;
    asm("{ .reg .u64 t; cvta.to.shared.u64 t, %1; cvt.u32.u64 %0, t; }"
        : "=r"(a) : "l"(p));
    return a;
}
__device__ __forceinline__ void ldsm4(uint32_t& r0, uint32_t& r1, uint32_t& r2,
                                      uint32_t& r3, uint32_t addr) {
    asm volatile("ldmatrix.sync.aligned.m8n8.x4.shared.b16 {%0,%1,%2,%3}, [%4];"
                 : "=r"(r0), "=r"(r1), "=r"(r2), "=r"(r3) : "r"(addr));
}
__device__ __forceinline__ void ldsm4t(uint32_t& r0, uint32_t& r1, uint32_t& r2,
                                       uint32_t& r3, uint32_t addr) {
    asm volatile("ldmatrix.sync.aligned.m8n8.x4.trans.shared.b16 {%0,%1,%2,%3}, [%4];"
                 : "=r"(r0), "=r"(r1), "=r"(r2), "=r"(r3) : "r"(addr));
}
__device__ __forceinline__ void mma_bf16(float* c, const uint32_t* a,
                                         uint32_t b0, uint32_t b1) {
    asm volatile(
        "mma.sync.aligned.m16n8k16.row.col.f32.bf16.bf16.f32 "
        "{%0,%1,%2,%3}, {%4,%5,%6,%7}, {%8,%9}, {%0,%1,%2,%3};"
        : "+f"(c[0]), "+f"(c[1]), "+f"(c[2]), "+f"(c[3])
        : "r"(a[0]), "r"(a[1]), "r"(a[2]), "r"(a[3]), "r"(b0), "r"(b1));
}
__device__ __forceinline__ void cpa16(uint32_t dst, const void* src) {
    asm volatile("cp.async.cg.shared.global [%0], [%1], 16;" :: "r"(dst), "l"(src));
}
#define CP_COMMIT() asm volatile("cp.async.commit_group;" ::: "memory")
#define CP_WAIT(n)  asm volatile("cp.async.wait_group %0;" :: "n"(n) : "memory")

__device__ __forceinline__ void split2(float v0, float v1, uint32_t& hi, uint32_t& lo) {
    __nv_bfloat16 h0 = __float2bfloat16(v0), h1 = __float2bfloat16(v1);
    float r0 = v0 - __bfloat162float(h0);
    float r1 = v1 - __bfloat162float(h1);
    __nv_bfloat16 l0 = __float2bfloat16(r0), l1 = __float2bfloat16(r1);
    hi = (uint32_t)__bfloat16_as_ushort(h0) | ((uint32_t)__bfloat16_as_ushort(h1) << 16);
    lo = (uint32_t)__bfloat16_as_ushort(l0) | ((uint32_t)__bfloat16_as_ushort(l1) << 16);
}

// ---------------------------------------------------------------------------
// Prepass: fp32 -> bf16 hi/lo arrays
// ---------------------------------------------------------------------------
__global__ void conv_split(const float* __restrict__ src,
                           __nv_bfloat16* __restrict__ hi,
                           __nv_bfloat16* __restrict__ lo, int n)
{
    int idx = (blockIdx.x * blockDim.x + threadIdx.x) * 4;
    if (idx >= n) return;
    float4 v = *(const float4*)(src + idx);
    uint32_t h0, l0, h1, l1;
    split2(v.x, v.y, h0, l0);
    split2(v.z, v.w, h1, l1);
    *(uint2*)(hi + idx) = make_uint2(h0, h1);
    *(uint2*)(lo + idx) = make_uint2(l0, l1);
}

// ---------------------------------------------------------------------------
// Pipelined bf16x3 GEMM. BM=BN=128, BK=32, 3-stage cp.async, 2 CTAs/SM.
// Swizzled zero-pad smem: A rows 64B (4 quads, q^=(r>>1)&3),
//                         B rows 256B (16 quads, q^=r&7).
// Split terms are the OUTER loop so successive MMAs hit different accumulators.
// ---------------------------------------------------------------------------
#define SA_HI 0
#define SA_LO 8192
#define SB_HI 16384
#define SB_LO 24576
#define STAGE_SZ 32768
#define G_SMEM (STAGE_SZ * 3)

__global__ __launch_bounds__(256, 2)
void gemm_tc(const __nv_bfloat16* __restrict__ Ahi, const __nv_bfloat16* __restrict__ Alo,
             const __nv_bfloat16* __restrict__ Bhi, const __nv_bfloat16* __restrict__ Blo,
             const float* __restrict__ bias,
             float* __restrict__ Cf,
             __nv_bfloat16* __restrict__ Chi, __nv_bfloat16* __restrict__ Clo,
             int M, int N, int K)
{
    extern __shared__ char sm[];
    const uint32_t smb = smem_u32(sm);
    const int tid = threadIdx.x;
    const int w = tid >> 5, lane = tid & 31;
    const int wm = w >> 2, wn = w & 3;
    const int row0 = blockIdx.y * 128, col0 = blockIdx.x * 128;

    float acc[4][4][4];
    #pragma unroll
    for (int a = 0; a < 4; a++)
        #pragma unroll
        for (int b = 0; b < 4; b++)
            #pragma unroll
            for (int cc = 0; cc < 4; cc++) acc[a][b][cc] = 0.0f;

    const int nchunk = K >> 5;

    #define G_ISSUE(kc)                                                         \
    do {                                                                        \
        uint32_t base = smb + ((kc) % 3) * STAGE_SZ;                            \
        _Pragma("unroll")                                                       \
        for (int l = 0; l < 2; l++) {                                           \
            int slot = tid + l * 256;                                           \
            int ar = slot >> 2, aq = slot & 3;                                  \
            uint32_t aoff = (uint32_t)(ar * 64 + ((aq ^ ((ar >> 1) & 3)) << 4));\
            size_t ga = (size_t)(row0 + ar) * K + (kc) * 32 + aq * 8;           \
            cpa16(base + SA_HI + aoff, Ahi + ga);                               \
            cpa16(base + SA_LO + aoff, Alo + ga);                               \
            int br = slot >> 4, bq = slot & 15;                                 \
            uint32_t boff = (uint32_t)(br * 256 + ((bq ^ (br & 7)) << 4));      \
            size_t gb = (size_t)((kc) * 32 + br) * N + col0 + bq * 8;           \
            cpa16(base + SB_HI + boff, Bhi + gb);                               \
            cpa16(base + SB_LO + boff, Blo + gb);                               \
        }                                                                       \
    } while (0)

    G_ISSUE(0); CP_COMMIT();
    G_ISSUE(1); CP_COMMIT();

    for (int kc = 0; kc < nchunk; kc++) {
        CP_WAIT(1);
        __syncthreads();
        if (kc + 2 < nchunk) G_ISSUE(kc + 2);
        CP_COMMIT();

        const uint32_t sbase = smb + (kc % 3) * STAGE_SZ;
        const int arow = wm * 64 + (lane & 15);
        #pragma unroll
        for (int ks = 0; ks < 2; ks++) {
            uint32_t ah[4][4], al[4][4], bh[2][4], bl[2][4];
            const int aq = ks * 2 + (lane >> 4);
            const uint32_t aswz = (uint32_t)((aq ^ ((arow >> 1) & 3)) << 4);
            #pragma unroll
            for (int tm = 0; tm < 4; tm++) {
                uint32_t ad = sbase + (uint32_t)((arow + tm * 16) * 64) + aswz;
                ldsm4(ah[tm][0], ah[tm][1], ah[tm][2], ah[tm][3], ad + SA_HI);
                ldsm4(al[tm][0], al[tm][1], al[tm][2], al[tm][3], ad + SA_LO);
            }
            const int brow = ks * 16 + (lane & 7) + (lane & 8);
            #pragma unroll
            for (int t2 = 0; t2 < 2; t2++) {
                int bq = wn * 4 + (lane >> 4) + t2 * 2;
                uint32_t bd = sbase + (uint32_t)(brow * 256 + ((bq ^ (lane & 7)) << 4));
                ldsm4t(bh[t2][0], bh[t2][1], bh[t2][2], bh[t2][3], bd + SB_HI);
                ldsm4t(bl[t2][0], bl[t2][1], bl[t2][2], bl[t2][3], bd + SB_LO);
            }
            // term-outer ordering: 16 independent accumulators between RAW reuse
            #pragma unroll
            for (int tm = 0; tm < 4; tm++)
                #pragma unroll
                for (int tn = 0; tn < 4; tn++)
                    mma_bf16(acc[tm][tn], ah[tm],
                             bh[tn >> 1][(tn & 1) * 2], bh[tn >> 1][(tn & 1) * 2 + 1]);
            #pragma unroll
            for (int tm = 0; tm < 4; tm++)
                #pragma unroll
                for (int tn = 0; tn < 4; tn++)
                    mma_bf16(acc[tm][tn], ah[tm],
                             bl[tn >> 1][(tn & 1) * 2], bl[tn >> 1][(tn & 1) * 2 + 1]);
            #pragma unroll
            for (int tm = 0; tm < 4; tm++)
                #pragma unroll
                for (int tn = 0; tn < 4; tn++)
                    mma_bf16(acc[tm][tn], al[tm],
                             bh[tn >> 1][(tn & 1) * 2], bh[tn >> 1][(tn & 1) * 2 + 1]);
        }
    }

    #pragma unroll
    for (int tm = 0; tm < 4; tm++) {
        int r = row0 + wm * 64 + tm * 16 + (lane >> 2);
        #pragma unroll
        for (int tn = 0; tn < 4; tn++) {
            int c = col0 + wn * 32 + tn * 8 + 2 * (lane & 3);
            float2 bv = *(const float2*)(bias + c);
            float c0 = acc[tm][tn][0] + bv.x, c1 = acc[tm][tn][1] + bv.y;
            float c2 = acc[tm][tn][2] + bv.x, c3 = acc[tm][tn][3] + bv.y;
            if (Cf) {
                *(float2*)(Cf + (size_t)r * N + c) = make_float2(c0, c1);
                *(float2*)(Cf + (size_t)(r + 8) * N + c) = make_float2(c2, c3);
            } else {
                uint32_t h0, l0, h1, l1;
                split2(c0, c1, h0, l0);
                split2(c2, c3, h1, l1);
                *(uint32_t*)(Chi + (size_t)r * N + c) = h0;
                *(uint32_t*)(Clo + (size_t)r * N + c) = l0;
                *(uint32_t*)(Chi + (size_t)(r + 8) * N + c) = h1;
                *(uint32_t*)(Clo + (size_t)(r + 8) * N + c) = l1;
            }
        }
    }
}

// ---------------------------------------------------------------------------
// Attention (bf16x3): per (128-row tile i, head h). S = tril(QK^T), O += S@V.
// Swizzled tiles (rows 128B, q^=r&7), S rows 256B (q^=(r&7)<<1).
// Double-buffered K/V via cp.async prefetch. Term-outer MMA ordering.
// ---------------------------------------------------------------------------
#define AQ_HI 0
#define AQ_LO 16384
#define AKV(buf) (32768 + (buf) * 65536)   // +0 Khi, +16K Klo, +32K Vhi, +48K Vlo
#define AS_HI 163840
#define AS_LO 196608
#define A_SMEM 229376

__global__ __launch_bounds__(256, 1)
void attn_tc(const __nv_bfloat16* __restrict__ kqvhi,
             const __nv_bfloat16* __restrict__ kqvlo,
             __nv_bfloat16* __restrict__ atthi,
             __nv_bfloat16* __restrict__ attlo)
{
    extern __shared__ char sm[];
    const uint32_t smb = smem_u32(sm);
    const int tid = threadIdx.x;
    const int w = tid >> 5, lane = tid & 31;
    const int wm = w >> 2, wn = w & 3;
    const int i = 31 - blockIdx.x;          // heavy tiles first
    const int h = blockIdx.y;
    const int row0 = i * 128;
    const int ldg = 3 * D_EMBD;

    const __nv_bfloat16* qhi = kqvhi + D_EMBD + h * D_HEAD;   // order: k, q, v
    const __nv_bfloat16* qlo = kqvlo + D_EMBD + h * D_HEAD;
    const __nv_bfloat16* khi = kqvhi + h * D_HEAD;
    const __nv_bfloat16* klo = kqvlo + h * D_HEAD;
    const __nv_bfloat16* vhi = kqvhi + 2 * D_EMBD + h * D_HEAD;
    const __nv_bfloat16* vlo = kqvlo + 2 * D_EMBD + h * D_HEAD;

    #define KV_ISSUE(jblk, buf)                                                 \
    do {                                                                        \
        uint32_t kb = smb + AKV(buf);                                           \
        _Pragma("unroll")                                                       \
        for (int l = 0; l < 4; l++) {                                           \
            int slot = tid + l * 256;                                           \
            int r = slot >> 3, q = slot & 7;                                    \
            uint32_t d = (uint32_t)(r * 128 + ((q ^ (r & 7)) << 4));            \
            size_t go = (size_t)((jblk) * 128 + r) * ldg + q * 8;               \
            cpa16(kb + d, khi + go);                                            \
            cpa16(kb + 16384 + d, klo + go);                                    \
            cpa16(kb + 32768 + d, vhi + go);                                    \
            cpa16(kb + 49152 + d, vlo + go);                                    \
        }                                                                       \
    } while (0)

    // Q tile
    #pragma unroll
    for (int l = 0; l < 4; l++) {
        int slot = tid + l * 256;
        int r = slot >> 3, q = slot & 7;
        uint32_t d = (uint32_t)(r * 128 + ((q ^ (r & 7)) << 4));
        size_t go = (size_t)(row0 + r) * ldg + q * 8;
        cpa16(smb + AQ_HI + d, qhi + go);
        cpa16(smb + AQ_LO + d, qlo + go);
    }
    KV_ISSUE(0, 0);
    CP_COMMIT();

    float oacc[4][2][4];
    #pragma unroll
    for (int a = 0; a < 4; a++)
        #pragma unroll
        for (int b = 0; b < 2; b++)
            #pragma unroll
            for (int cc = 0; cc < 4; cc++) oacc[a][b][cc] = 0.0f;

    for (int j = 0; j <= i; j++) {
        CP_WAIT(0);
        __syncthreads();
        if (j < i) { KV_ISSUE(j + 1, (j + 1) & 1); CP_COMMIT(); }

        const uint32_t kvb = smb + AKV(j & 1);

        // ---- S = Q @ K^T (warp tile 64x32, kdim 64) ----
        float sacc[4][4][4];
        #pragma unroll
        for (int a = 0; a < 4; a++)
            #pragma unroll
            for (int b = 0; b < 4; b++)
                #pragma unroll
                for (int cc = 0; cc < 4; cc++) sacc[a][b][cc] = 0.0f;

        const int arow = wm * 64 + (lane & 15);
        #pragma unroll
        for (int ks = 0; ks < 4; ks++) {
            uint32_t ah[4][4], al[4][4], bh[2][4], bl[2][4];
            const int aq = ks * 2 + (lane >> 4);
            const uint32_t aswz = (uint32_t)((aq ^ (arow & 7)) << 4);
            #pragma unroll
            for (int tm = 0; tm < 4; tm++) {
                uint32_t ad = smb + (uint32_t)((arow + tm * 16) * 128) + aswz;
                ldsm4(ah[tm][0], ah[tm][1], ah[tm][2], ah[tm][3], ad + AQ_HI);
                ldsm4(al[tm][0], al[tm][1], al[tm][2], al[tm][3], ad + AQ_LO);
            }
            const int krow0 = wn * 32 + (lane & 7) + ((lane >> 1) & 8);
            const int kq = ks * 2 + ((lane >> 3) & 1);
            const uint32_t kswz = (uint32_t)((kq ^ (lane & 7)) << 4);
            #pragma unroll
            for (int t2 = 0; t2 < 2; t2++) {
                uint32_t bd = kvb + (uint32_t)((krow0 + t2 * 16) * 128) + kswz;
                ldsm4(bh[t2][0], bh[t2][1], bh[t2][2], bh[t2][3], bd);
                ldsm4(bl[t2][0], bl[t2][1], bl[t2][2], bl[t2][3], bd + 16384);
            }
            #pragma unroll
            for (int tm = 0; tm < 4; tm++)
                #pragma unroll
                for (int tn = 0; tn < 4; tn++)
                    mma_bf16(sacc[tm][tn], ah[tm],
                             bh[tn >> 1][(tn & 1) * 2], bh[tn >> 1][(tn & 1) * 2 + 1]);
            #pragma unroll
            for (int tm = 0; tm < 4; tm++)
                #pragma unroll
                for (int tn = 0; tn < 4; tn++)
                    mma_bf16(sacc[tm][tn], ah[tm],
                             bl[tn >> 1][(tn & 1) * 2], bl[tn >> 1][(tn & 1) * 2 + 1]);
            #pragma unroll
            for (int tm = 0; tm < 4; tm++)
                #pragma unroll
                for (int tn = 0; tn < 4; tn++)
                    mma_bf16(sacc[tm][tn], al[tm],
                             bh[tn >> 1][(tn & 1) * 2], bh[tn >> 1][(tn & 1) * 2 + 1]);
        }

        // ---- mask (diag block only) + split S to hi/lo smem ----
        {
            const bool diag = (j == i);
            #pragma unroll
            for (int tm = 0; tm < 4; tm++) {
                int rl = wm * 64 + tm * 16 + (lane >> 2);
                const uint32_t rsw = (uint32_t)((rl & 7) << 1);
                #pragma unroll
                for (int tn = 0; tn < 4; tn++) {
                    int cl = wn * 32 + tn * 8 + 2 * (lane & 3);
                    float c0 = sacc[tm][tn][0], c1 = sacc[tm][tn][1];
                    float c2 = sacc[tm][tn][2], c3 = sacc[tm][tn][3];
                    if (diag) {
                        if (cl     > rl)     c0 = 0.0f;
                        if (cl + 1 > rl)     c1 = 0.0f;
                        if (cl     > rl + 8) c2 = 0.0f;
                        if (cl + 1 > rl + 8) c3 = 0.0f;
                    }
                    uint32_t h0, l0, h1, l1;
                    split2(c0, c1, h0, l0);
                    split2(c2, c3, h1, l1);
                    int q = wn * 4 + tn;
                    uint32_t off0 = (uint32_t)(rl * 256 + ((q ^ rsw) << 4) + 4 * (lane & 3));
                    uint32_t off1 = (uint32_t)((rl + 8) * 256 + ((q ^ rsw) << 4) + 4 * (lane & 3));
                    *(uint32_t*)(sm + AS_HI + off0) = h0;
                    *(uint32_t*)(sm + AS_LO + off0) = l0;
                    *(uint32_t*)(sm + AS_HI + off1) = h1;
                    *(uint32_t*)(sm + AS_LO + off1) = l1;
                }
            }
        }
        __syncthreads();

        // ---- O += S @ V (warp tile 64x16, kdim 128) ----
        #pragma unroll
        for (int ks = 0; ks < 8; ks++) {
            uint32_t ah[4][4], al[4][4], bh[4], bl[4];
            const int aq = ks * 2 + (lane >> 4);
            const uint32_t aswz = (uint32_t)((aq ^ ((lane & 7) << 1)) << 4);
            #pragma unroll
            for (int tm = 0; tm < 4; tm++) {
                uint32_t ad = smb + (uint32_t)((arow + tm * 16) * 256) + aswz;
                ldsm4(ah[tm][0], ah[tm][1], ah[tm][2], ah[tm][3], ad + AS_HI);
                ldsm4(al[tm][0], al[tm][1], al[tm][2], al[tm][3], ad + AS_LO);
            }
            const int vrow = ks * 16 + (lane & 7) + (lane & 8);
            const int vq = wn * 2 + (lane >> 4);
            uint32_t bd = kvb + 32768 +
                          (uint32_t)(vrow * 128 + ((vq ^ (lane & 7)) << 4));
            ldsm4t(bh[0], bh[1], bh[2], bh[3], bd);
            ldsm4t(bl[0], bl[1], bl[2], bl[3], bd + 16384);
            #pragma unroll
            for (int tm = 0; tm < 4; tm++)
                #pragma unroll
                for (int tn = 0; tn < 2; tn++)
                    mma_bf16(oacc[tm][tn], ah[tm], bh[tn * 2], bh[tn * 2 + 1]);
            #pragma unroll
            for (int tm = 0; tm < 4; tm++)
                #pragma unroll
                for (int tn = 0; tn < 2; tn++)
                    mma_bf16(oacc[tm][tn], ah[tm], bl[tn * 2], bl[tn * 2 + 1]);
            #pragma unroll
            for (int tm = 0; tm < 4; tm++)
                #pragma unroll
                for (int tn = 0; tn < 2; tn++)
                    mma_bf16(oacc[tm][tn], al[tm], bh[tn * 2], bh[tn * 2 + 1]);
        }
    }

    // ---- epilogue: O -> att hi/lo (t, h*d layout) ----
    #pragma unroll
    for (int tm = 0; tm < 4; tm++) {
        int r = row0 + wm * 64 + tm * 16 + (lane >> 2);
        #pragma unroll
        for (int tn = 0; tn < 2; tn++) {
            int c = h * D_HEAD + wn * 16 + tn * 8 + 2 * (lane & 3);
            uint32_t h0, l0, h1, l1;
            split2(oacc[tm][tn][0], oacc[tm][tn][1], h0, l0);
            split2(oacc[tm][tn][2], oacc[tm][tn][3], h1, l1);
            *(uint32_t*)(atthi + (size_t)r * D_EMBD + c) = h0;
            *(uint32_t*)(attlo + (size_t)r * D_EMBD + c) = l0;
            *(uint32_t*)(atthi + (size_t)(r + 8) * D_EMBD + c) = h1;
            *(uint32_t*)(attlo + (size_t)(r + 8) * D_EMBD + c) = l1;
        }
    }
}

// ---------------------------------------------------------------------------
extern "C" void kernel_launch(void* const* d_in, const int* in_sizes, int n_in,
                              void* d_out, int out_size)
{
    const float* x  = (const float*)d_in[0];
    const float* W1 = (const float*)d_in[1];
    const float* b1 = (const float*)d_in[2];
    const float* W2 = (const float*)d_in[3];
    const float* b2 = (const float*)d_in[4];
    float* out = (float*)d_out;

    __nv_bfloat16 *xhi, *xlo, *w1hi, *w1lo, *w2hi, *w2lo, *kqvhi, *kqvlo, *atthi, *attlo;
    cudaGetSymbolAddress((void**)&xhi, g_xhi);
    cudaGetSymbolAddress((void**)&xlo, g_xlo);
    cudaGetSymbolAddress((void**)&w1hi, g_w1hi);
    cudaGetSymbolAddress((void**)&w1lo, g_w1lo);
    cudaGetSymbolAddress((void**)&w2hi, g_w2hi);
    cudaGetSymbolAddress((void**)&w2lo, g_w2lo);
    cudaGetSymbolAddress((void**)&kqvhi, g_kqvhi);
    cudaGetSymbolAddress((void**)&kqvlo, g_kqvlo);
    cudaGetSymbolAddress((void**)&atthi, g_atthi);
    cudaGetSymbolAddress((void**)&attlo, g_attlo);

    cudaFuncSetAttribute(gemm_tc, cudaFuncAttributeMaxDynamicSharedMemorySize, G_SMEM);
    cudaFuncSetAttribute(attn_tc, cudaFuncAttributeMaxDynamicSharedMemorySize, A_SMEM);

    int nx = T_SEQ * D_EMBD, nw1 = D_EMBD * 3 * D_EMBD, nw2 = D_EMBD * D_EMBD;
    conv_split<<<nx / 1024, 256>>>(x, xhi, xlo, nx);
    conv_split<<<nw1 / 1024, 256>>>(W1, w1hi, w1lo, nw1);
    conv_split<<<nw2 / 1024, 256>>>(W2, w2hi, w2lo, nw2);

    gemm_tc<<<dim3(3 * D_EMBD / 128, T_SEQ / 128), 256, G_SMEM>>>(
        xhi, xlo, w1hi, w1lo, b1, nullptr, kqvhi, kqvlo,
        T_SEQ, 3 * D_EMBD, D_EMBD);

    attn_tc<<<dim3(T_SEQ / 128, N_HEADS), 256, A_SMEM>>>(kqvhi, kqvlo, atthi, attlo);

    gemm_tc<<<dim3(D_EMBD / 128, T_SEQ / 128), 256, G_SMEM>>>(
        atthi, attlo, w2hi, w2lo, b2, out, nullptr, nullptr,
        T_SEQ, D_EMBD, D_EMBD);
}

// round 7
// speedup vs baseline: 3.4233x; 1.1742x over previous
#include <cuda_runtime.h>
#include <cuda_bf16.h>
#include <cstdint>

#define T_SEQ   4096
#define D_EMBD  1024
#define N_HEADS 16
#define D_HEAD  64

// bf16 hi/lo split scratch (device globals — no runtime allocation allowed)
__device__ __nv_bfloat16 g_xhi[(size_t)T_SEQ * D_EMBD];
__device__ __nv_bfloat16 g_xlo[(size_t)T_SEQ * D_EMBD];
__device__ __nv_bfloat16 g_w1hi[(size_t)D_EMBD * 3 * D_EMBD];
__device__ __nv_bfloat16 g_w1lo[(size_t)D_EMBD * 3 * D_EMBD];
__device__ __nv_bfloat16 g_w2hi[(size_t)D_EMBD * D_EMBD];
__device__ __nv_bfloat16 g_w2lo[(size_t)D_EMBD * D_EMBD];
__device__ __nv_bfloat16 g_kqvhi[(size_t)T_SEQ * 3 * D_EMBD];
__device__ __nv_bfloat16 g_kqvlo[(size_t)T_SEQ * 3 * D_EMBD];
__device__ __nv_bfloat16 g_atthi[(size_t)T_SEQ * D_EMBD];
__device__ __nv_bfloat16 g_attlo[(size_t)T_SEQ * D_EMBD];

// ---------------------------------------------------------------------------
// Helpers
// ---------------------------------------------------------------------------
__device__ __forceinline__ uint32_t smem_u32(const void* p) {
    uint32_t a;
    asm("{ .reg .u64 t; cvta.to.shared.u64 t, %1; cvt.u32.u64 %0, t; }"
        : "=r"(a) : "l"(p));
    return a;
}
__device__ __forceinline__ void ldsm4(uint32_t* r, uint32_t addr) {
    asm volatile("ldmatrix.sync.aligned.m8n8.x4.shared.b16 {%0,%1,%2,%3}, [%4];"
                 : "=r"(r[0]), "=r"(r[1]), "=r"(r[2]), "=r"(r[3]) : "r"(addr));
}
__device__ __forceinline__ void ldsm4t(uint32_t* r, uint32_t addr) {
    asm volatile("ldmatrix.sync.aligned.m8n8.x4.trans.shared.b16 {%0,%1,%2,%3}, [%4];"
                 : "=r"(r[0]), "=r"(r[1]), "=r"(r[2]), "=r"(r[3]) : "r"(addr));
}
__device__ __forceinline__ void mma_bf16(float* c, const uint32_t* a,
                                         uint32_t b0, uint32_t b1) {
    asm volatile(
        "mma.sync.aligned.m16n8k16.row.col.f32.bf16.bf16.f32 "
        "{%0,%1,%2,%3}, {%4,%5,%6,%7}, {%8,%9}, {%0,%1,%2,%3};"
        : "+f"(c[0]), "+f"(c[1]), "+f"(c[2]), "+f"(c[3])
        : "r"(a[0]), "r"(a[1]), "r"(a[2]), "r"(a[3]), "r"(b0), "r"(b1));
}
__device__ __forceinline__ void cpa16(uint32_t dst, const void* src) {
    asm volatile("cp.async.cg.shared.global [%0], [%1], 16;" :: "r"(dst), "l"(src));
}
#define CP_COMMIT() asm volatile("cp.async.commit_group;" ::: "memory")
#define CP_WAIT(n)  asm volatile("cp.async.wait_group %0;" :: "n"(n) : "memory")

__device__ __forceinline__ void split2(float v0, float v1, uint32_t& hi, uint32_t& lo) {
    __nv_bfloat16 h0 = __float2bfloat16(v0), h1 = __float2bfloat16(v1);
    float r0 = v0 - __bfloat162float(h0);
    float r1 = v1 - __bfloat162float(h1);
    __nv_bfloat16 l0 = __float2bfloat16(r0), l1 = __float2bfloat16(r1);
    hi = (uint32_t)__bfloat16_as_ushort(h0) | ((uint32_t)__bfloat16_as_ushort(h1) << 16);
    lo = (uint32_t)__bfloat16_as_ushort(l0) | ((uint32_t)__bfloat16_as_ushort(l1) << 16);
}

// ---------------------------------------------------------------------------
// Prepass: fp32 -> bf16 hi/lo arrays
// ---------------------------------------------------------------------------
__global__ void conv_split(const float* __restrict__ src,
                           __nv_bfloat16* __restrict__ hi,
                           __nv_bfloat16* __restrict__ lo, int n)
{
    int idx = (blockIdx.x * blockDim.x + threadIdx.x) * 4;
    if (idx >= n) return;
    float4 v = *(const float4*)(src + idx);
    uint32_t h0, l0, h1, l1;
    split2(v.x, v.y, h0, l0);
    split2(v.z, v.w, h1, l1);
    *(uint2*)(hi + idx) = make_uint2(h0, h1);
    *(uint2*)(lo + idx) = make_uint2(l0, l1);
}

// ---------------------------------------------------------------------------
// Pipelined bf16x3 GEMM. BM=BN=128, BK=32, 3-stage cp.async, 2 CTAs/SM.
// ---------------------------------------------------------------------------
#define SA_HI 0
#define SA_LO 8192
#define SB_HI 16384
#define SB_LO 24576
#define STAGE_SZ 32768
#define G_SMEM (STAGE_SZ * 3)

__global__ __launch_bounds__(256, 2)
void gemm_tc(const __nv_bfloat16* __restrict__ Ahi, const __nv_bfloat16* __restrict__ Alo,
             const __nv_bfloat16* __restrict__ Bhi, const __nv_bfloat16* __restrict__ Blo,
             const float* __restrict__ bias,
             float* __restrict__ Cf,
             __nv_bfloat16* __restrict__ Chi, __nv_bfloat16* __restrict__ Clo,
             int M, int N, int K)
{
    extern __shared__ char sm[];
    const uint32_t smb = smem_u32(sm);
    const int tid = threadIdx.x;
    const int w = tid >> 5, lane = tid & 31;
    const int wm = w >> 2, wn = w & 3;
    const int row0 = blockIdx.y * 128, col0 = blockIdx.x * 128;

    float acc[4][4][4];
    #pragma unroll
    for (int a = 0; a < 4; a++)
        #pragma unroll
        for (int b = 0; b < 4; b++)
            #pragma unroll
            for (int cc = 0; cc < 4; cc++) acc[a][b][cc] = 0.0f;

    const int nchunk = K >> 5;

    #define G_ISSUE(kc)                                                         \
    do {                                                                        \
        uint32_t base = smb + ((kc) % 3) * STAGE_SZ;                            \
        _Pragma("unroll")                                                       \
        for (int l = 0; l < 2; l++) {                                           \
            int slot = tid + l * 256;                                           \
            int ar = slot >> 2, aq = slot & 3;                                  \
            uint32_t aoff = (uint32_t)(ar * 64 + ((aq ^ ((ar >> 1) & 3)) << 4));\
            size_t ga = (size_t)(row0 + ar) * K + (kc) * 32 + aq * 8;           \
            cpa16(base + SA_HI + aoff, Ahi + ga);                               \
            cpa16(base + SA_LO + aoff, Alo + ga);                               \
            int br = slot >> 4, bq = slot & 15;                                 \
            uint32_t boff = (uint32_t)(br * 256 + ((bq ^ (br & 7)) << 4));      \
            size_t gb = (size_t)((kc) * 32 + br) * N + col0 + bq * 8;           \
            cpa16(base + SB_HI + boff, Bhi + gb);                               \
            cpa16(base + SB_LO + boff, Blo + gb);                               \
        }                                                                       \
    } while (0)

    G_ISSUE(0); CP_COMMIT();
    G_ISSUE(1); CP_COMMIT();

    for (int kc = 0; kc < nchunk; kc++) {
        CP_WAIT(1);
        __syncthreads();
        if (kc + 2 < nchunk) G_ISSUE(kc + 2);
        CP_COMMIT();

        const uint32_t sbase = smb + (kc % 3) * STAGE_SZ;
        const int arow = wm * 64 + (lane & 15);
        #pragma unroll
        for (int ks = 0; ks < 2; ks++) {
            uint32_t ah[4][4], al[4][4], bh[2][4], bl[2][4];
            const int aq = ks * 2 + (lane >> 4);
            const uint32_t aswz = (uint32_t)((aq ^ ((arow >> 1) & 3)) << 4);
            #pragma unroll
            for (int tm = 0; tm < 4; tm++) {
                uint32_t ad = sbase + (uint32_t)((arow + tm * 16) * 64) + aswz;
                ldsm4(ah[tm], ad + SA_HI);
                ldsm4(al[tm], ad + SA_LO);
            }
            const int brow = ks * 16 + (lane & 7) + (lane & 8);
            #pragma unroll
            for (int t2 = 0; t2 < 2; t2++) {
                int bq = wn * 4 + (lane >> 4) + t2 * 2;
                uint32_t bd = sbase + (uint32_t)(brow * 256 + ((bq ^ (lane & 7)) << 4));
                ldsm4t(bh[t2], bd + SB_HI);
                ldsm4t(bl[t2], bd + SB_LO);
            }
            #pragma unroll
            for (int tm = 0; tm < 4; tm++)
                #pragma unroll
                for (int tn = 0; tn < 4; tn++) {
                    mma_bf16(acc[tm][tn], ah[tm],
                             bh[tn >> 1][(tn & 1) * 2], bh[tn >> 1][(tn & 1) * 2 + 1]);
                    mma_bf16(acc[tm][tn], ah[tm],
                             bl[tn >> 1][(tn & 1) * 2], bl[tn >> 1][(tn & 1) * 2 + 1]);
                    mma_bf16(acc[tm][tn], al[tm],
                             bh[tn >> 1][(tn & 1) * 2], bh[tn >> 1][(tn & 1) * 2 + 1]);
                }
        }
    }

    #pragma unroll
    for (int tm = 0; tm < 4; tm++) {
        int r = row0 + wm * 64 + tm * 16 + (lane >> 2);
        #pragma unroll
        for (int tn = 0; tn < 4; tn++) {
            int c = col0 + wn * 32 + tn * 8 + 2 * (lane & 3);
            float2 bv = *(const float2*)(bias + c);
            float c0 = acc[tm][tn][0] + bv.x, c1 = acc[tm][tn][1] + bv.y;
            float c2 = acc[tm][tn][2] + bv.x, c3 = acc[tm][tn][3] + bv.y;
            if (Cf) {
                *(float2*)(Cf + (size_t)r * N + c) = make_float2(c0, c1);
                *(float2*)(Cf + (size_t)(r + 8) * N + c) = make_float2(c2, c3);
            } else {
                uint32_t h0, l0, h1, l1;
                split2(c0, c1, h0, l0);
                split2(c2, c3, h1, l1);
                *(uint32_t*)(Chi + (size_t)r * N + c) = h0;
                *(uint32_t*)(Clo + (size_t)r * N + c) = l0;
                *(uint32_t*)(Chi + (size_t)(r + 8) * N + c) = h1;
                *(uint32_t*)(Clo + (size_t)(r + 8) * N + c) = l1;
            }
        }
    }
}

// ---------------------------------------------------------------------------
// Attention (bf16x3), register-resident S (FA2-style fragment reuse).
// 8 warps = 4 row-groups (32 rows) x 2 key-halves (64 keys).
// S = tril(QK^T) in regs -> mask -> split -> A-frags for O += S@V (k-partial).
// One cross-warp k-reduction through smem after the j-loop.
// ---------------------------------------------------------------------------
#define AQ_HI 0
#define AQ_LO 16384
#define AKV(buf) (32768 + (buf) * 65536)   // +0 Khi, +16K Klo, +32K Vhi, +48K Vlo
#define A_RED 32768                        // reduction buffer (reuses KV buf0)
#define A_SMEM 163840

__global__ __launch_bounds__(256, 1)
void attn_tc(const __nv_bfloat16* __restrict__ kqvhi,
             const __nv_bfloat16* __restrict__ kqvlo,
             __nv_bfloat16* __restrict__ atthi,
             __nv_bfloat16* __restrict__ attlo)
{
    extern __shared__ char sm[];
    const uint32_t smb = smem_u32(sm);
    const int tid = threadIdx.x;
    const int w = tid >> 5, lane = tid & 31;
    const int wr = w >> 1;                  // row group 0..3 (32 rows each)
    const int wk = w & 1;                   // key half 0..1 (64 keys each)
    const int i = 31 - blockIdx.x;          // heavy tiles first
    const int h = blockIdx.y;
    const int row0 = i * 128;
    const int ldg = 3 * D_EMBD;

    const __nv_bfloat16* qhi = kqvhi + D_EMBD + h * D_HEAD;   // order: k, q, v
    const __nv_bfloat16* qlo = kqvlo + D_EMBD + h * D_HEAD;
    const __nv_bfloat16* khi = kqvhi + h * D_HEAD;
    const __nv_bfloat16* klo = kqvlo + h * D_HEAD;
    const __nv_bfloat16* vhi = kqvhi + 2 * D_EMBD + h * D_HEAD;
    const __nv_bfloat16* vlo = kqvlo + 2 * D_EMBD + h * D_HEAD;

    #define KV_ISSUE(jblk, buf)                                                 \
    do {                                                                        \
        uint32_t kb = smb + AKV(buf);                                           \
        _Pragma("unroll")                                                       \
        for (int l = 0; l < 4; l++) {                                           \
            int slot = tid + l * 256;                                           \
            int r = slot >> 3, q = slot & 7;                                    \
            uint32_t d = (uint32_t)(r * 128 + ((q ^ (r & 7)) << 4));            \
            size_t go = (size_t)((jblk) * 128 + r) * ldg + q * 8;               \
            cpa16(kb + d, khi + go);                                            \
            cpa16(kb + 16384 + d, klo + go);                                    \
            cpa16(kb + 32768 + d, vhi + go);                                    \
            cpa16(kb + 49152 + d, vlo + go);                                    \
        }                                                                       \
    } while (0)

    // Q tile
    #pragma unroll
    for (int l = 0; l < 4; l++) {
        int slot = tid + l * 256;
        int r = slot >> 3, q = slot & 7;
        uint32_t d = (uint32_t)(r * 128 + ((q ^ (r & 7)) << 4));
        size_t go = (size_t)(row0 + r) * ldg + q * 8;
        cpa16(smb + AQ_HI + d, qhi + go);
        cpa16(smb + AQ_LO + d, qlo + go);
    }
    KV_ISSUE(0, 0);
    CP_COMMIT();
    CP_WAIT(0);
    __syncthreads();

    float oacc[2][8][4];
    #pragma unroll
    for (int a = 0; a < 2; a++)
        #pragma unroll
        for (int b = 0; b < 8; b++)
            #pragma unroll
            for (int cc = 0; cc < 4; cc++) oacc[a][b][cc] = 0.0f;

    for (int j = 0; j <= i; j++) {
        if (j > 0) { CP_WAIT(0); }
        __syncthreads();
        if (j < i) { KV_ISSUE(j + 1, (j + 1) & 1); CP_COMMIT(); }

        const uint32_t kvb = smb + AKV(j & 1);

        // ---- S = Q @ K^T: warp tile 32 rows x 64 keys, kdim 64, in regs ----
        float sacc[2][8][4];
        #pragma unroll
        for (int a = 0; a < 2; a++)
            #pragma unroll
            for (int b = 0; b < 8; b++)
                #pragma unroll
                for (int cc = 0; cc < 4; cc++) sacc[a][b][cc] = 0.0f;

        #pragma unroll
        for (int ks = 0; ks < 4; ks++) {
            uint32_t qa_h[2][4], qa_l[2][4], kb_h[4][4], kb_l[4][4];
            const int aq = ks * 2 + (lane >> 4);
            const uint32_t aswz = (uint32_t)((aq ^ (lane & 7)) << 4);
            #pragma unroll
            for (int rt = 0; rt < 2; rt++) {
                uint32_t ad = smb + (uint32_t)((wr * 32 + rt * 16 + (lane & 15)) * 128) + aswz;
                ldsm4(qa_h[rt], ad + AQ_HI);
                ldsm4(qa_l[rt], ad + AQ_LO);
            }
            const int kq = ks * 2 + ((lane >> 3) & 1);
            const uint32_t kswz = (uint32_t)((kq ^ (lane & 7)) << 4);
            #pragma unroll
            for (int g = 0; g < 4; g++) {
                int krow = wk * 64 + g * 16 + (lane & 7) + ((lane >> 1) & 8);
                uint32_t bd = kvb + (uint32_t)(krow * 128) + kswz;
                ldsm4(kb_h[g], bd);
                ldsm4(kb_l[g], bd + 16384);
            }
            #pragma unroll
            for (int rt = 0; rt < 2; rt++)
                #pragma unroll
                for (int nt = 0; nt < 8; nt++) {
                    uint32_t b0h = kb_h[nt >> 1][(nt & 1) * 2], b1h = kb_h[nt >> 1][(nt & 1) * 2 + 1];
                    uint32_t b0l = kb_l[nt >> 1][(nt & 1) * 2], b1l = kb_l[nt >> 1][(nt & 1) * 2 + 1];
                    mma_bf16(sacc[rt][nt], qa_h[rt], b0h, b1h);
                    mma_bf16(sacc[rt][nt], qa_h[rt], b0l, b1l);
                    mma_bf16(sacc[rt][nt], qa_l[rt], b0h, b1h);
                }
        }

        // ---- causal mask (diag block only), in registers ----
        if (j == i) {
            #pragma unroll
            for (int rt = 0; rt < 2; rt++) {
                int rl = wr * 32 + rt * 16 + (lane >> 2);
                #pragma unroll
                for (int nt = 0; nt < 8; nt++) {
                    int cl = wk * 64 + nt * 8 + 2 * (lane & 3);
                    if (cl     > rl)     sacc[rt][nt][0] = 0.0f;
                    if (cl + 1 > rl)     sacc[rt][nt][1] = 0.0f;
                    if (cl     > rl + 8) sacc[rt][nt][2] = 0.0f;
                    if (cl + 1 > rl + 8) sacc[rt][nt][3] = 0.0f;
                }
            }
        }

        // ---- O += S @ V: S fragments straight from registers ----
        #pragma unroll
        for (int ksl = 0; ksl < 4; ksl++) {
            uint32_t sa_h[2][4], sa_l[2][4], vb_h[4][4], vb_l[4][4];
            #pragma unroll
            for (int rt = 0; rt < 2; rt++) {
                split2(sacc[rt][2 * ksl][0],     sacc[rt][2 * ksl][1],     sa_h[rt][0], sa_l[rt][0]);
                split2(sacc[rt][2 * ksl][2],     sacc[rt][2 * ksl][3],     sa_h[rt][1], sa_l[rt][1]);
                split2(sacc[rt][2 * ksl + 1][0], sacc[rt][2 * ksl + 1][1], sa_h[rt][2], sa_l[rt][2]);
                split2(sacc[rt][2 * ksl + 1][2], sacc[rt][2 * ksl + 1][3], sa_h[rt][3], sa_l[rt][3]);
            }
            const int vrow = wk * 64 + ksl * 16 + (lane & 7) + (lane & 8);
            #pragma unroll
            for (int g2 = 0; g2 < 4; g2++) {
                int vq = g2 * 2 + (lane >> 4);
                uint32_t vd = kvb + 32768 +
                              (uint32_t)(vrow * 128 + ((vq ^ (lane & 7)) << 4));
                ldsm4t(vb_h[g2], vd);
                ldsm4t(vb_l[g2], vd + 16384);
            }
            #pragma unroll
            for (int rt = 0; rt < 2; rt++)
                #pragma unroll
                for (int nt = 0; nt < 8; nt++) {
                    uint32_t b0h = vb_h[nt >> 1][(nt & 1) * 2], b1h = vb_h[nt >> 1][(nt & 1) * 2 + 1];
                    uint32_t b0l = vb_l[nt >> 1][(nt & 1) * 2], b1l = vb_l[nt >> 1][(nt & 1) * 2 + 1];
                    mma_bf16(oacc[rt][nt], sa_h[rt], b0h, b1h);
                    mma_bf16(oacc[rt][nt], sa_h[rt], b0l, b1l);
                    mma_bf16(oacc[rt][nt], sa_l[rt], b0h, b1h);
                }
        }
    }

    // ---- cross-warp k-reduction (wk=1 -> smem, wk=0 adds) + epilogue ----
    __syncthreads();
    if (wk == 1) {
        #pragma unroll
        for (int rt = 0; rt < 2; rt++) {
            int r = wr * 32 + rt * 16 + (lane >> 2);
            #pragma unroll
            for (int nt = 0; nt < 8; nt++) {
                int c = nt * 8 + 2 * (lane & 3);
                *(float2*)(sm + A_RED + (size_t)(r * 64 + c) * 4) =
                    make_float2(oacc[rt][nt][0], oacc[rt][nt][1]);
                *(float2*)(sm + A_RED + (size_t)((r + 8) * 64 + c) * 4) =
                    make_float2(oacc[rt][nt][2], oacc[rt][nt][3]);
            }
        }
    }
    __syncthreads();
    if (wk == 0) {
        #pragma unroll
        for (int rt = 0; rt < 2; rt++) {
            int rl = wr * 32 + rt * 16 + (lane >> 2);
            int r = row0 + rl;
            #pragma unroll
            for (int nt = 0; nt < 8; nt++) {
                int cl = nt * 8 + 2 * (lane & 3);
                int c = h * D_HEAD + cl;
                float2 p0 = *(const float2*)(sm + A_RED + (size_t)(rl * 64 + cl) * 4);
                float2 p1 = *(const float2*)(sm + A_RED + (size_t)((rl + 8) * 64 + cl) * 4);
                float c0 = oacc[rt][nt][0] + p0.x, c1 = oacc[rt][nt][1] + p0.y;
                float c2 = oacc[rt][nt][2] + p1.x, c3 = oacc[rt][nt][3] + p1.y;
                uint32_t h0, l0, h1, l1;
                split2(c0, c1, h0, l0);
                split2(c2, c3, h1, l1);
                *(uint32_t*)(atthi + (size_t)r * D_EMBD + c) = h0;
                *(uint32_t*)(attlo + (size_t)r * D_EMBD + c) = l0;
                *(uint32_t*)(atthi + (size_t)(r + 8) * D_EMBD + c) = h1;
                *(uint32_t*)(attlo + (size_t)(r + 8) * D_EMBD + c) = l1;
            }
        }
    }
}

// ---------------------------------------------------------------------------
extern "C" void kernel_launch(void* const* d_in, const int* in_sizes, int n_in,
                              void* d_out, int out_size)
{
    const float* x  = (const float*)d_in[0];
    const float* W1 = (const float*)d_in[1];
    const float* b1 = (const float*)d_in[2];
    const float* W2 = (const float*)d_in[3];
    const float* b2 = (const float*)d_in[4];
    float* out = (float*)d_out;

    __nv_bfloat16 *xhi, *xlo, *w1hi, *w1lo, *w2hi, *w2lo, *kqvhi, *kqvlo, *atthi, *attlo;
    cudaGetSymbolAddress((void**)&xhi, g_xhi);
    cudaGetSymbolAddress((void**)&xlo, g_xlo);
    cudaGetSymbolAddress((void**)&w1hi, g_w1hi);
    cudaGetSymbolAddress((void**)&w1lo, g_w1lo);
    cudaGetSymbolAddress((void**)&w2hi, g_w2hi);
    cudaGetSymbolAddress((void**)&w2lo, g_w2lo);
    cudaGetSymbolAddress((void**)&kqvhi, g_kqvhi);
    cudaGetSymbolAddress((void**)&kqvlo, g_kqvlo);
    cudaGetSymbolAddress((void**)&atthi, g_atthi);
    cudaGetSymbolAddress((void**)&attlo, g_attlo);

    cudaFuncSetAttribute(gemm_tc, cudaFuncAttributeMaxDynamicSharedMemorySize, G_SMEM);
    cudaFuncSetAttribute(attn_tc, cudaFuncAttributeMaxDynamicSharedMemorySize, A_SMEM);

    int nx = T_SEQ * D_EMBD, nw1 = D_EMBD * 3 * D_EMBD, nw2 = D_EMBD * D_EMBD;
    conv_split<<<nx / 1024, 256>>>(x, xhi, xlo, nx);
    conv_split<<<nw1 / 1024, 256>>>(W1, w1hi, w1lo, nw1);
    conv_split<<<nw2 / 1024, 256>>>(W2, w2hi, w2lo, nw2);

    gemm_tc<<<dim3(3 * D_EMBD / 128, T_SEQ / 128), 256, G_SMEM>>>(
        xhi, xlo, w1hi, w1lo, b1, nullptr, kqvhi, kqvlo,
        T_SEQ, 3 * D_EMBD, D_EMBD);

    attn_tc<<<dim3(T_SEQ / 128, N_HEADS), 256, A_SMEM>>>(kqvhi, kqvlo, atthi, attlo);

    gemm_tc<<<dim3(D_EMBD / 128, T_SEQ / 128), 256, G_SMEM>>>(
        atthi, attlo, w2hi, w2lo, b2, out, nullptr, nullptr,
        T_SEQ, D_EMBD, D_EMBD);
}